// round 14
// baseline (speedup 1.0000x reference)
#include <cuda_runtime.h>
#include <math.h>

#define NEGB -1.0e30f

// ----------------- scratch -----------------
__device__ float g_pool[67108864];
__device__ float g_pos1[8*2048*3];
__device__ float g_pos2[8*512*3];
__device__ int   g_nidx1[8*2048*64];
__device__ int   g_cnt1[8*2048];
__device__ int   g_nidx2[8*512*64];
__device__ int   g_cnt2[8*512];
__device__ float g_x1[8*2048*128];
__device__ float g_x2cat[8*512*259];
__device__ float g_g1[8*512*256];
__device__ float g_g2[8*512*512];
__device__ float g_gmx[128*1024];
__device__ float g_f1[128*512];
__device__ float g_f2[128*256];
__device__ float g_f3[32*7];

// ---- packed f32x2 helpers ----
__device__ __forceinline__ unsigned long long pk2(float lo, float hi) {
    unsigned long long r; asm("mov.b64 %0, {%1, %2};" : "=l"(r) : "f"(lo), "f"(hi)); return r;
}
__device__ __forceinline__ void upk2(unsigned long long v, float& lo, float& hi) {
    asm("mov.b64 {%0, %1}, %2;" : "=f"(lo), "=f"(hi) : "l"(v));
}
__device__ __forceinline__ unsigned long long add2(unsigned long long a, unsigned long long b) {
    unsigned long long r; asm("add.rn.f32x2 %0, %1, %2;" : "=l"(r) : "l"(a), "l"(b)); return r;
}
__device__ __forceinline__ unsigned long long mul2(unsigned long long a, unsigned long long b) {
    unsigned long long r; asm("mul.rn.f32x2 %0, %1, %2;" : "=l"(r) : "l"(a), "l"(b)); return r;
}

// ---- tf32 mma helpers ----
__device__ __forceinline__ unsigned f2tf(float f) {
    unsigned r; asm("cvt.rna.tf32.f32 %0, %1;" : "=r"(r) : "f"(f)); return r;
}
__device__ __forceinline__ void mma8(float c[4], unsigned a0, unsigned a1, unsigned a2, unsigned a3,
                                     unsigned b0, unsigned b1) {
    asm volatile("mma.sync.aligned.m16n8k8.row.col.f32.tf32.tf32.f32 "
                 "{%0,%1,%2,%3},{%4,%5,%6,%7},{%8,%9},{%0,%1,%2,%3};"
                 : "+f"(c[0]), "+f"(c[1]), "+f"(c[2]), "+f"(c[3])
                 : "r"(a0), "r"(a1), "r"(a2), "r"(a3), "r"(b0), "r"(b1));
}

// ----------------- FPS v6: 256 threads (2 warps/SMSP), tree bv --------------
template<int PT>
__global__ __launch_bounds__(256) void fps_kernel(const float* __restrict__ posIn,
                                                  float* __restrict__ posOut,
                                                  int N, int S)
{
    extern __shared__ float sm[];
    float* spx = sm;
    float* spy = sm + N;
    float* spz = sm + 2*N;
    unsigned long long* part = (unsigned long long*)(sm + 3*N);  // [2][8]

    int b = blockIdx.x, t = threadIdx.x;
    int lane = t & 31, warp = t >> 5;
    const float* p = posIn + (size_t)b*N*3;
    unsigned long long pxp[PT/2], pyp[PT/2], pzp[PT/2];
    float mind[PT];
    #pragma unroll
    for (int jj = 0; jj < PT/2; jj++) {
        int i0 = (2*jj)*256 + t, i1 = (2*jj+1)*256 + t;
        float x0 = p[3*i0], y0 = p[3*i0+1], z0 = p[3*i0+2];
        float x1 = p[3*i1], y1 = p[3*i1+1], z1 = p[3*i1+2];
        spx[i0] = x0; spy[i0] = y0; spz[i0] = z0;
        spx[i1] = x1; spy[i1] = y1; spz[i1] = z1;
        pxp[jj] = pk2(x0, x1); pyp[jj] = pk2(y0, y1); pzp[jj] = pk2(z0, z1);
        mind[2*jj] = 3.402823466e38f; mind[2*jj+1] = 3.402823466e38f;
    }
    if (t == 0) {
        float* o = posOut + (size_t)b*S*3;
        o[0] = p[0]; o[1] = p[1]; o[2] = p[2];
    }
    __syncthreads();
    int bidx = 0;
    for (int s = 1; s < S; s++) {
        float lx = spx[bidx], ly = spy[bidx], lz = spz[bidx];
        unsigned long long nx = pk2(-lx, -lx), ny = pk2(-ly, -ly), nz = pk2(-lz, -lz);
        float bva[4] = {NEGB, NEGB, NEGB, NEGB};
        #pragma unroll
        for (int jj = 0; jj < PT/2; jj++) {
            unsigned long long dx = add2(pxp[jj], nx);
            unsigned long long dy = add2(pyp[jj], ny);
            unsigned long long dz = add2(pzp[jj], nz);
            unsigned long long d2 = add2(add2(mul2(dx,dx), mul2(dy,dy)), mul2(dz,dz));
            float dlo, dhi; upk2(d2, dlo, dhi);
            float m0 = fminf(mind[2*jj],   dlo); mind[2*jj]   = m0;
            float m1 = fminf(mind[2*jj+1], dhi); mind[2*jj+1] = m1;
            bva[jj & 3] = fmaxf(bva[jj & 3], fmaxf(m0, m1));
        }
        float bv = fmaxf(fmaxf(bva[0], bva[1]), fmaxf(bva[2], bva[3]));
        unsigned vb = __float_as_uint(bv);
        unsigned vmax = __reduce_max_sync(0xffffffffu, vb);
        int cand = 0x7fffffff;
        if (vb == vmax) {
            #pragma unroll
            for (int j = PT-1; j >= 0; j--)
                if (__float_as_uint(mind[j]) == vmax) cand = j*256 + t;
        }
        int widx = __reduce_min_sync(0xffffffffu, cand);
        if (lane == 0)
            part[(s & 1)*8 + warp] =
                ((unsigned long long)vmax << 32) | (unsigned)(0xFFFFFFFFu - (unsigned)widx);
        __syncthreads();
        const unsigned long long* pp = part + (s & 1)*8;
        unsigned long long k0 = pp[0], k1 = pp[1], k2 = pp[2], k3 = pp[3];
        unsigned long long k4 = pp[4], k5 = pp[5], k6 = pp[6], k7 = pp[7];
        k0 = k0 > k1 ? k0 : k1;  k2 = k2 > k3 ? k2 : k3;
        k4 = k4 > k5 ? k4 : k5;  k6 = k6 > k7 ? k6 : k7;
        k0 = k0 > k2 ? k0 : k2;  k4 = k4 > k6 ? k4 : k6;
        k0 = k0 > k4 ? k0 : k4;
        bidx = (int)(0xFFFFFFFFu - (unsigned)(k0 & 0xFFFFFFFFu));
        if (t == 0) {
            float* o = posOut + ((size_t)b*S + s)*3;
            o[0] = spx[bidx]; o[1] = spy[bidx]; o[2] = spz[bidx];
        }
    }
}

// ----------------- radius NN (unchanged, exact) -----------------
__global__ void radius_kernel(const float* __restrict__ posAll, const float* __restrict__ posQ,
                              int N, int M, float r2,
                              int* __restrict__ nidx, int* __restrict__ cnt)
{
    __shared__ unsigned long long cand[8][256];
    __shared__ int scnt[8];
    int warp = threadIdx.x >> 5, lane = threadIdx.x & 31;
    int q = blockIdx.x * 8 + warp;
    int b = q / M;
    if (lane == 0) scnt[warp] = 0;
    __syncwarp();
    const float* qp = posQ + (size_t)q*3;
    float qx = qp[0], qy = qp[1], qz = qp[2];
    const float* p = posAll + (size_t)b*N*3;
    for (int i = lane; i < N; i += 32) {
        float dx = __fsub_rn(qx, p[3*i]);
        float dy = __fsub_rn(qy, p[3*i+1]);
        float dz = __fsub_rn(qz, p[3*i+2]);
        float d2 = __fadd_rn(__fadd_rn(__fmul_rn(dx,dx), __fmul_rn(dy,dy)), __fmul_rn(dz,dz));
        if (d2 <= r2) {
            int pos = atomicAdd(&scnt[warp], 1);
            if (pos < 256)
                cand[warp][pos] = ((unsigned long long)__float_as_uint(d2) << 32) | (unsigned)i;
        }
    }
    __syncwarp();
    int c = scnt[warp]; if (c > 256) c = 256;
    int* out = nidx + (size_t)q*64;
    if (c <= 64) {
        for (int t = lane; t < c; t += 32) out[t] = (int)(cand[warp][t] & 0xffffffffu);
        if (lane == 0) cnt[q] = c;
    } else {
        int slots = (c + 31) >> 5;
        for (int sel = 0; sel < 64; sel++) {
            unsigned long long best = ~0ULL;
            for (int k = 0; k < slots; k++) {
                int j = lane + (k << 5);
                if (j < c) { unsigned long long v = cand[warp][j]; if (v < best) best = v; }
            }
            #pragma unroll
            for (int off = 16; off; off >>= 1) {
                unsigned long long o = __shfl_down_sync(0xffffffffu, best, off);
                if (o < best) best = o;
            }
            best = __shfl_sync(0xffffffffu, best, 0);
            if (lane == 0) out[sel] = (int)(best & 0xffffffffu);
            for (int k = 0; k < slots; k++) {
                int j = lane + (k << 5);
                if (j < c && cand[warp][j] == best) cand[warp][j] = ~0ULL;
            }
        }
        if (lane == 0) cnt[q] = 64;
    }
}

// ============ Stage-1: scalar layer1 + tf32 mma layers 2/3, QPB=4 ============
__global__ __launch_bounds__(256) void s1_fused(const float* __restrict__ pts,
    const float* __restrict__ w1, const float* __restrict__ b1,
    const float* __restrict__ w2, const float* __restrict__ b2,
    const float* __restrict__ w3, const float* __restrict__ b3)
{
    extern __shared__ unsigned usm[];
    unsigned* uW2 = usm;                // 64 x 72
    unsigned* uW3 = usm + 4608;         // 64 x 136
    unsigned* uH1 = usm + 13312;        // 64 x 76
    unsigned* uH2 = usm + 18176;        // 64 x 76
    float* fW1  = (float*)(usm + 23040);
    float* fB1  = (float*)(usm + 23232);
    float* fB2  = (float*)(usm + 23296);
    float* fB3  = (float*)(usm + 23360);
    float* fRel = (float*)(usm + 23488);
    float* fPart= (float*)(usm + 23744);

    int tid = threadIdx.x;
    int lane = tid & 31, w = tid >> 5;
    int t4 = lane >> 2, tm4 = lane & 3;
    int r0 = (w & 3) * 16;

    for (int i = tid; i < 192;  i += 256) fW1[i] = w1[i];
    for (int i = tid; i < 64;   i += 256) { fB1[i] = b1[i]; fB2[i] = b2[i]; }
    if (tid < 128) fB3[tid] = b3[tid];
    for (int i = tid; i < 4608; i += 256) {
        int k = i / 72, n = i - k*72;
        uW2[i] = (n < 64) ? f2tf(w2[k*64 + n]) : 0u;
    }
    for (int i = tid; i < 8704; i += 256) {
        int k = i / 136, n = i - k*136;
        uW3[i] = (n < 128) ? f2tf(w3[k*128 + n]) : 0u;
    }

    for (int qi = 0; qi < 4; qi++) {
        int q = blockIdx.x*4 + qi;
        int b = q >> 11;
        int cnt = g_cnt1[q];
        if (tid < 64) {
            int idx = (tid < cnt) ? g_nidx1[q*64 + tid] : 0;
            const float* sp = pts + ((size_t)b*4096 + idx)*3;
            const float* qp = g_pos1 + (size_t)q*3;
            fRel[tid*4+0] = sp[0] - qp[0];
            fRel[tid*4+1] = sp[1] - qp[1];
            fRel[tid*4+2] = sp[2] - qp[2];
        }
        __syncthreads();
        {
            int m = tid >> 2, j0 = (tid & 3) * 16;
            float rx = fRel[m*4], ry = fRel[m*4+1], rz = fRel[m*4+2];
            #pragma unroll
            for (int j = 0; j < 16; j++) {
                int c = j0 + j;
                float v = fmaf(rz, fW1[128+c], fmaf(ry, fW1[64+c], fmaf(rx, fW1[c], fB1[c])));
                uH1[m*76 + c] = f2tf(fmaxf(v, 0.f));
            }
        }
        __syncthreads();
        int active = (r0 < cnt);
        if (active) {
            int c0 = (w >> 2) * 32;
            float acc[4][4];
            #pragma unroll
            for (int nt = 0; nt < 4; nt++) { acc[nt][0]=acc[nt][1]=acc[nt][2]=acc[nt][3]=0.f; }
            #pragma unroll
            for (int kk = 0; kk < 64; kk += 8) {
                unsigned a0 = uH1[(r0+t4)*76   + kk + tm4];
                unsigned a1 = uH1[(r0+t4+8)*76 + kk + tm4];
                unsigned a2 = uH1[(r0+t4)*76   + kk + tm4 + 4];
                unsigned a3 = uH1[(r0+t4+8)*76 + kk + tm4 + 4];
                #pragma unroll
                for (int nt = 0; nt < 4; nt++) {
                    int cb = c0 + nt*8 + t4;
                    unsigned bb0 = uW2[(kk+tm4)*72   + cb];
                    unsigned bb1 = uW2[(kk+tm4+4)*72 + cb];
                    mma8(acc[nt], a0, a1, a2, a3, bb0, bb1);
                }
            }
            #pragma unroll
            for (int nt = 0; nt < 4; nt++) {
                int col = c0 + nt*8 + 2*tm4;
                uH2[(r0+t4)*76   + col]   = f2tf(fmaxf(acc[nt][0] + fB2[col],   0.f));
                uH2[(r0+t4)*76   + col+1] = f2tf(fmaxf(acc[nt][1] + fB2[col+1], 0.f));
                uH2[(r0+t4+8)*76 + col]   = f2tf(fmaxf(acc[nt][2] + fB2[col],   0.f));
                uH2[(r0+t4+8)*76 + col+1] = f2tf(fmaxf(acc[nt][3] + fB2[col+1], 0.f));
            }
        }
        __syncthreads();
        if (active) {
            int c0 = (w >> 2) * 64;
            float acc[8][4];
            #pragma unroll
            for (int nt = 0; nt < 8; nt++) { acc[nt][0]=acc[nt][1]=acc[nt][2]=acc[nt][3]=0.f; }
            #pragma unroll
            for (int kk = 0; kk < 64; kk += 8) {
                unsigned a0 = uH2[(r0+t4)*76   + kk + tm4];
                unsigned a1 = uH2[(r0+t4+8)*76 + kk + tm4];
                unsigned a2 = uH2[(r0+t4)*76   + kk + tm4 + 4];
                unsigned a3 = uH2[(r0+t4+8)*76 + kk + tm4 + 4];
                #pragma unroll
                for (int nt = 0; nt < 8; nt++) {
                    int cb = c0 + nt*8 + t4;
                    unsigned bb0 = uW3[(kk+tm4)*136   + cb];
                    unsigned bb1 = uW3[(kk+tm4+4)*136 + cb];
                    mma8(acc[nt], a0, a1, a2, a3, bb0, bb1);
                }
            }
            bool oka = (r0 + t4) < cnt, okb = (r0 + t4 + 8) < cnt;
            #pragma unroll
            for (int nt = 0; nt < 8; nt++) {
                int col = c0 + nt*8 + 2*tm4;
                float m0 = oka ? (acc[nt][0] + fB3[col])   : NEGB;
                float m1 = oka ? (acc[nt][1] + fB3[col+1]) : NEGB;
                if (okb) {
                    m0 = fmaxf(m0, acc[nt][2] + fB3[col]);
                    m1 = fmaxf(m1, acc[nt][3] + fB3[col+1]);
                }
                #pragma unroll
                for (int off = 16; off >= 4; off >>= 1) {
                    m0 = fmaxf(m0, __shfl_xor_sync(0xffffffffu, m0, off));
                    m1 = fmaxf(m1, __shfl_xor_sync(0xffffffffu, m1, off));
                }
                if (t4 == 0) {
                    fPart[(w&3)*128 + col]     = m0;
                    fPart[(w&3)*128 + col + 1] = m1;
                }
            }
        }
        __syncthreads();
        if (tid < 128) {
            int nrt = (cnt + 15) >> 4; if (nrt > 4) nrt = 4;
            float m = NEGB;
            for (int r = 0; r < nrt; r++) m = fmaxf(m, fPart[r*128 + tid]);
            g_x1[(size_t)q*128 + tid] = fmaxf(m, 0.f);
        }
        __syncthreads();
    }
}

// ============ Stage-2 part A: tf32 mma (131->128->128), QPB=4 ================
__global__ __launch_bounds__(256) void s2a_fused(
    const float* __restrict__ w1, const float* __restrict__ b1,
    const float* __restrict__ w2, const float* __restrict__ b2,
    float* __restrict__ h2out)
{
    extern __shared__ unsigned usm[];
    unsigned* uW1 = usm;
    unsigned* uW2 = usm + 18496;
    unsigned* uA  = usm + 35904;
    unsigned* uH1 = usm + 44864;
    float* fb1 = (float*)(usm + 53824);
    float* fb2 = (float*)(usm + 53952);

    int tid = threadIdx.x;
    int lane = tid & 31, w = tid >> 5;
    int t4 = lane >> 2, tm4 = lane & 3;
    int r0 = (w & 3) * 16, c0 = (w >> 2) * 64;

    for (int i = tid; i < 18496; i += 256) {
        int k = i / 136, n = i - k*136;
        uW1[i] = (k < 131 && n < 128) ? f2tf(w1[k*128 + n]) : 0u;
    }
    for (int i = tid; i < 17408; i += 256) {
        int k = i / 136, n = i - k*136;
        uW2[i] = (n < 128) ? f2tf(w2[k*128 + n]) : 0u;
    }
    if (tid < 128) { fb1[tid] = b1[tid]; fb2[tid] = b2[tid]; }

    for (int qi = 0; qi < 4; qi++) {
        int q = blockIdx.x*4 + qi;
        int b = q >> 9;
        int cnt = g_cnt2[q];
        {
            int m = tid >> 2, l4 = tid & 3;
            int idx = (m < cnt) ? g_nidx2[q*64 + m] : 0;
            const float4* src = (const float4*)(g_x1 + ((size_t)b*2048 + idx)*128);
            #pragma unroll
            for (int j = 0; j < 8; j++) {
                float4 v = src[l4*8 + j];
                unsigned* d = uA + m*140 + l4*32 + j*4;
                d[0] = f2tf(v.x); d[1] = f2tf(v.y); d[2] = f2tf(v.z); d[3] = f2tf(v.w);
            }
            if (l4 == 0) {
                const float* ps = g_pos1 + ((size_t)b*2048 + idx)*3;
                const float* pq = g_pos2 + (size_t)q*3;
                uA[m*140+128] = f2tf(ps[0]-pq[0]);
                uA[m*140+129] = f2tf(ps[1]-pq[1]);
                uA[m*140+130] = f2tf(ps[2]-pq[2]);
                #pragma unroll
                for (int z = 131; z < 140; z++) uA[m*140+z] = 0u;
            }
        }
        __syncthreads();
        {
            float C1[8][4];
            #pragma unroll
            for (int nt = 0; nt < 8; nt++) { C1[nt][0]=C1[nt][1]=C1[nt][2]=C1[nt][3]=0.f; }
            for (int ks = 0; ks < 17; ks++) {
                int k0 = ks*8;
                unsigned a0 = uA[(r0+t4)*140   + k0 + tm4];
                unsigned a1 = uA[(r0+t4+8)*140 + k0 + tm4];
                unsigned a2 = uA[(r0+t4)*140   + k0 + tm4 + 4];
                unsigned a3 = uA[(r0+t4+8)*140 + k0 + tm4 + 4];
                #pragma unroll
                for (int nt = 0; nt < 8; nt++) {
                    int cb = c0 + nt*8 + t4;
                    unsigned bb0 = uW1[(k0+tm4)*136   + cb];
                    unsigned bb1 = uW1[(k0+tm4+4)*136 + cb];
                    mma8(C1[nt], a0, a1, a2, a3, bb0, bb1);
                }
            }
            #pragma unroll
            for (int nt = 0; nt < 8; nt++) {
                int col = c0 + nt*8 + 2*tm4;
                uH1[(r0+t4)*140   + col]   = f2tf(fmaxf(C1[nt][0] + fb1[col],   0.f));
                uH1[(r0+t4)*140   + col+1] = f2tf(fmaxf(C1[nt][1] + fb1[col+1], 0.f));
                uH1[(r0+t4+8)*140 + col]   = f2tf(fmaxf(C1[nt][2] + fb1[col],   0.f));
                uH1[(r0+t4+8)*140 + col+1] = f2tf(fmaxf(C1[nt][3] + fb1[col+1], 0.f));
            }
        }
        __syncthreads();
        {
            float C2[8][4];
            #pragma unroll
            for (int nt = 0; nt < 8; nt++) { C2[nt][0]=C2[nt][1]=C2[nt][2]=C2[nt][3]=0.f; }
            for (int ks = 0; ks < 16; ks++) {
                int k0 = ks*8;
                unsigned a0 = uH1[(r0+t4)*140   + k0 + tm4];
                unsigned a1 = uH1[(r0+t4+8)*140 + k0 + tm4];
                unsigned a2 = uH1[(r0+t4)*140   + k0 + tm4 + 4];
                unsigned a3 = uH1[(r0+t4+8)*140 + k0 + tm4 + 4];
                #pragma unroll
                for (int nt = 0; nt < 8; nt++) {
                    int cb = c0 + nt*8 + t4;
                    unsigned bb0 = uW2[(k0+tm4)*136   + cb];
                    unsigned bb1 = uW2[(k0+tm4+4)*136 + cb];
                    mma8(C2[nt], a0, a1, a2, a3, bb0, bb1);
                }
            }
            #pragma unroll
            for (int nt = 0; nt < 8; nt++) {
                int col = c0 + nt*8 + 2*tm4;
                float2 va = make_float2(fmaxf(C2[nt][0] + fb2[col],   0.f),
                                        fmaxf(C2[nt][1] + fb2[col+1], 0.f));
                float2 vb = make_float2(fmaxf(C2[nt][2] + fb2[col],   0.f),
                                        fmaxf(C2[nt][3] + fb2[col+1], 0.f));
                *(float2*)(h2out + ((size_t)q*64 + r0+t4)*128   + col) = va;
                *(float2*)(h2out + ((size_t)q*64 + r0+t4+8)*128 + col) = vb;
            }
        }
        __syncthreads();
    }
}

// ============ Stage-2 part B: tf32 mma + masked max, QPB=4 ===================
__global__ __launch_bounds__(256) void s2b_fused(
    const float* __restrict__ h2, const float* __restrict__ w3, const float* __restrict__ b3)
{
    extern __shared__ unsigned usm[];
    unsigned* uW3 = usm;
    unsigned* uA  = usm + 33792;
    float* fb3   = (float*)(usm + 42240);
    float* sPart = (float*)(usm + 42496);

    int tid = threadIdx.x;
    int lane = tid & 31, w = tid >> 5;
    int t4 = lane >> 2, tm4 = lane & 3;
    int r0 = (w & 3) * 16, c0 = (w >> 2) * 128;

    for (int i = tid; i < 33792; i += 256) {
        int k = i / 264, n = i - k*264;
        uW3[i] = (n < 256) ? f2tf(w3[k*256 + n]) : 0u;
    }
    if (tid < 256) fb3[tid] = b3[tid];

    for (int qi = 0; qi < 4; qi++) {
        int q = blockIdx.x*4 + qi;
        {
            int m = tid >> 2, l4 = tid & 3;
            const float4* src = (const float4*)(h2 + ((size_t)q*64 + m)*128);
            #pragma unroll
            for (int j = 0; j < 8; j++) {
                float4 v = src[l4*8 + j];
                unsigned* d = uA + m*132 + l4*32 + j*4;
                d[0] = f2tf(v.x); d[1] = f2tf(v.y); d[2] = f2tf(v.z); d[3] = f2tf(v.w);
            }
        }
        __syncthreads();
        int cnt = g_cnt2[q];
        float C[16][4];
        #pragma unroll
        for (int nt = 0; nt < 16; nt++) { C[nt][0]=C[nt][1]=C[nt][2]=C[nt][3]=0.f; }
        for (int ks = 0; ks < 16; ks++) {
            int k0 = ks*8;
            unsigned a0 = uA[(r0+t4)*132   + k0 + tm4];
            unsigned a1 = uA[(r0+t4+8)*132 + k0 + tm4];
            unsigned a2 = uA[(r0+t4)*132   + k0 + tm4 + 4];
            unsigned a3 = uA[(r0+t4+8)*132 + k0 + tm4 + 4];
            #pragma unroll
            for (int nt = 0; nt < 16; nt++) {
                int cb = c0 + nt*8 + t4;
                unsigned bb0 = uW3[(k0+tm4)*264   + cb];
                unsigned bb1 = uW3[(k0+tm4+4)*264 + cb];
                mma8(C[nt], a0, a1, a2, a3, bb0, bb1);
            }
        }
        bool oka = (r0 + t4) < cnt, okb = (r0 + t4 + 8) < cnt;
        #pragma unroll
        for (int nt = 0; nt < 16; nt++) {
            int col = c0 + nt*8 + 2*tm4;
            float m0 = oka ? (C[nt][0] + fb3[col])   : NEGB;
            float m1 = oka ? (C[nt][1] + fb3[col+1]) : NEGB;
            if (okb) {
                m0 = fmaxf(m0, C[nt][2] + fb3[col]);
                m1 = fmaxf(m1, C[nt][3] + fb3[col+1]);
            }
            #pragma unroll
            for (int off = 16; off >= 4; off >>= 1) {
                m0 = fmaxf(m0, __shfl_xor_sync(0xffffffffu, m0, off));
                m1 = fmaxf(m1, __shfl_xor_sync(0xffffffffu, m1, off));
            }
            if (t4 == 0) {
                sPart[(w&3)*256 + col]     = m0;
                sPart[(w&3)*256 + col + 1] = m1;
            }
        }
        __syncthreads();
        {
            float m = fmaxf(fmaxf(sPart[tid], sPart[256+tid]),
                            fmaxf(sPart[512+tid], sPart[768+tid]));
            g_x2cat[(size_t)q*259 + tid] = fmaxf(m, 0.f);
            if (tid < 3)
                g_x2cat[(size_t)q*259 + 256 + tid] = g_pos2[(size_t)q*3 + tid];
        }
        __syncthreads();
    }
}

// ============ tf32 GEMM (128x64 tile) with optional fused group-max ==========
template<int GMAX>
__global__ __launch_bounds__(256) void gemm_tf32(const float* __restrict__ A,
    const float* __restrict__ W, const float* __restrict__ bias,
    float* __restrict__ C, int M, int N, int K, int relu)
{
    __shared__ unsigned uA[128*20];
    __shared__ unsigned uW[16*72];
    __shared__ float sPart[4*64];
    int tid = threadIdx.x;
    int lane = tid & 31, w = tid >> 5;
    int t4 = lane >> 2, tm4 = lane & 3;
    int r0 = (w & 3) * 32, c0 = (w >> 2) * 32;
    int row0 = blockIdx.y * 128, col0 = blockIdx.x * 64;

    float acc[2][4][4];
    #pragma unroll
    for (int mt = 0; mt < 2; mt++)
        #pragma unroll
        for (int nt = 0; nt < 4; nt++)
            #pragma unroll
            for (int j = 0; j < 4; j++) acc[mt][nt][j] = 0.f;

    int nk = (K + 15) >> 4;
    for (int ks = 0; ks < nk; ks++) {
        int k0 = ks * 16;
        #pragma unroll
        for (int l = 0; l < 8; l++) {
            int idx = tid + l*256;
            int r = idx >> 4, c = idx & 15;
            int gc = k0 + c;
            uA[r*20 + c] = (gc < K) ? f2tf(A[(size_t)(row0 + r)*K + gc]) : 0u;
        }
        #pragma unroll
        for (int l = 0; l < 4; l++) {
            int idx = tid + l*256;
            int r = idx >> 6, c = idx & 63;
            int gr = k0 + r;
            uW[r*72 + c] = (gr < K) ? f2tf(W[(size_t)gr*N + col0 + c]) : 0u;
        }
        __syncthreads();
        #pragma unroll
        for (int kk = 0; kk < 16; kk += 8) {
            unsigned a0[2], a1[2], a2[2], a3[2];
            #pragma unroll
            for (int mt = 0; mt < 2; mt++) {
                a0[mt] = uA[(r0 + mt*16 + t4)*20   + kk + tm4];
                a1[mt] = uA[(r0 + mt*16 + t4+8)*20 + kk + tm4];
                a2[mt] = uA[(r0 + mt*16 + t4)*20   + kk + tm4 + 4];
                a3[mt] = uA[(r0 + mt*16 + t4+8)*20 + kk + tm4 + 4];
            }
            #pragma unroll
            for (int nt = 0; nt < 4; nt++) {
                int cb = c0 + nt*8 + t4;
                unsigned bb0 = uW[(kk+tm4)*72   + cb];
                unsigned bb1 = uW[(kk+tm4+4)*72 + cb];
                #pragma unroll
                for (int mt = 0; mt < 2; mt++)
                    mma8(acc[mt][nt], a0[mt], a1[mt], a2[mt], a3[mt], bb0, bb1);
            }
        }
        __syncthreads();
    }
    if (GMAX) {
        #pragma unroll
        for (int nt = 0; nt < 4; nt++) {
            int colr = c0 + nt*8 + 2*tm4;
            float bq0 = bias[col0 + colr], bq1 = bias[col0 + colr + 1];
            float m0 = fmaxf(fmaxf(acc[0][nt][0], acc[0][nt][2]),
                             fmaxf(acc[1][nt][0], acc[1][nt][2])) + bq0;
            float m1 = fmaxf(fmaxf(acc[0][nt][1], acc[0][nt][3]),
                             fmaxf(acc[1][nt][1], acc[1][nt][3])) + bq1;
            #pragma unroll
            for (int off = 16; off >= 4; off >>= 1) {
                m0 = fmaxf(m0, __shfl_xor_sync(0xffffffffu, m0, off));
                m1 = fmaxf(m1, __shfl_xor_sync(0xffffffffu, m1, off));
            }
            if (t4 == 0) {
                sPart[(w&3)*64 + colr]     = m0;
                sPart[(w&3)*64 + colr + 1] = m1;
            }
        }
        __syncthreads();
        if (tid < 64) {
            float m = fmaxf(fmaxf(sPart[tid], sPart[64+tid]),
                            fmaxf(sPart[128+tid], sPart[192+tid]));
            C[(size_t)blockIdx.y*1024 + col0 + tid] = m;
        }
    } else {
        #pragma unroll
        for (int mt = 0; mt < 2; mt++) {
            #pragma unroll
            for (int nt = 0; nt < 4; nt++) {
                int gc = col0 + c0 + nt*8 + 2*tm4;
                float v0 = acc[mt][nt][0] + bias[gc];
                float v1 = acc[mt][nt][1] + bias[gc+1];
                float v2 = acc[mt][nt][2] + bias[gc];
                float v3 = acc[mt][nt][3] + bias[gc+1];
                if (relu) {
                    v0 = fmaxf(v0, 0.f); v1 = fmaxf(v1, 0.f);
                    v2 = fmaxf(v2, 0.f); v3 = fmaxf(v3, 0.f);
                }
                int gr = row0 + r0 + mt*16 + t4;
                *(float2*)(C + (size_t)gr*N + gc)     = make_float2(v0, v1);
                *(float2*)(C + (size_t)(gr+8)*N + gc) = make_float2(v2, v3);
            }
        }
    }
}

// ----------------- scalar GEMM (final head layer) ----------------------------
__global__ void gemm_k(const float* __restrict__ A, const float* __restrict__ W,
                       const float* __restrict__ bias, float* __restrict__ C,
                       int M, int N, int K, int relu)
{
    __shared__ float As[16][132];
    __shared__ float Bs[16][64];
    int tid = threadIdx.x;
    int tr = tid >> 4, tc = tid & 15;
    int row0 = blockIdx.y * 128, col0 = blockIdx.x * 64;
    float acc[8][4];
    #pragma unroll
    for (int i = 0; i < 8; i++)
        #pragma unroll
        for (int j = 0; j < 4; j++) acc[i][j] = 0.f;
    for (int k0 = 0; k0 < K; k0 += 16) {
        #pragma unroll
        for (int l = 0; l < 8; l++) {
            int i = tid + l*256, r = i >> 4, c = i & 15;
            int gr = row0 + r, gc = k0 + c;
            As[c][r] = (gr < M && gc < K) ? A[(size_t)gr*K + gc] : 0.f;
        }
        #pragma unroll
        for (int l = 0; l < 4; l++) {
            int i = tid + l*256, r = i >> 6, c = i & 63;
            int gr = k0 + r, gc = col0 + c;
            Bs[r][c] = (gr < K && gc < N) ? W[(size_t)gr*N + gc] : 0.f;
        }
        __syncthreads();
        #pragma unroll
        for (int k = 0; k < 16; k++) {
            float a[8], bb[4];
            #pragma unroll
            for (int i = 0; i < 8; i++) a[i] = As[k][tr*8 + i];
            #pragma unroll
            for (int j = 0; j < 4; j++) bb[j] = Bs[k][tc*4 + j];
            #pragma unroll
            for (int i = 0; i < 8; i++)
                #pragma unroll
                for (int j = 0; j < 4; j++) acc[i][j] = fmaf(a[i], bb[j], acc[i][j]);
        }
        __syncthreads();
    }
    #pragma unroll
    for (int i = 0; i < 8; i++) {
        int gr = row0 + tr*8 + i;
        if (gr < M) {
            #pragma unroll
            for (int j = 0; j < 4; j++) {
                int gc = col0 + tc*4 + j;
                if (gc < N) {
                    float v = acc[i][j] + bias[gc];
                    if (relu) v = fmaxf(v, 0.f);
                    C[(size_t)gr*N + gc] = v;
                }
            }
        }
    }
}

__global__ void final_kernel(float* __restrict__ out)
{
    __shared__ float sm[8][7];
    int t = threadIdx.x;
    if (t < 56) {
        int b = t / 7, c = t % 7;
        float s = g_f3[(b*4)*7+c] + g_f3[(b*4+1)*7+c] + g_f3[(b*4+2)*7+c] + g_f3[(b*4+3)*7+c];
        sm[b][c] = s * 0.25f;
    }
    __syncthreads();
    if (t < 8) {
        float q0 = sm[t][3], q1 = sm[t][4], q2 = sm[t][5], q3 = sm[t][6];
        float nrm = sqrtf(q0*q0 + q1*q1 + q2*q2 + q3*q3);
        float d = fmaxf(nrm, 1e-12f);
        out[t*7+0] = sm[t][0]; out[t*7+1] = sm[t][1]; out[t*7+2] = sm[t][2];
        out[t*7+3] = q0/d; out[t*7+4] = q1/d; out[t*7+5] = q2/d; out[t*7+6] = q3/d;
    }
}

// ----------------- launcher --------------------------------------------------
extern "C" void kernel_launch(void* const* d_in, const int* in_sizes, int n_in,
                              void* d_out, int out_size)
{
    const float* pts  = (const float*)d_in[0];
    const float *s1w1 = (const float*)d_in[1],  *s1b1 = (const float*)d_in[2];
    const float *s1w2 = (const float*)d_in[3],  *s1b2 = (const float*)d_in[4];
    const float *s1w3 = (const float*)d_in[5],  *s1b3 = (const float*)d_in[6];
    const float *s2w1 = (const float*)d_in[7],  *s2b1 = (const float*)d_in[8];
    const float *s2w2 = (const float*)d_in[9],  *s2b2 = (const float*)d_in[10];
    const float *s2w3 = (const float*)d_in[11], *s2b3 = (const float*)d_in[12];
    const float *gw1  = (const float*)d_in[13], *gb1  = (const float*)d_in[14];
    const float *gw2  = (const float*)d_in[15], *gb2  = (const float*)d_in[16];
    const float *gw3  = (const float*)d_in[17], *gb3  = (const float*)d_in[18];
    const float *l1w  = (const float*)d_in[19], *l1b  = (const float*)d_in[20];
    const float *l2w  = (const float*)d_in[21], *l2b  = (const float*)d_in[22];
    const float *l3w  = (const float*)d_in[23], *l3b  = (const float*)d_in[24];

    float *pool, *pos1, *pos2, *x2cat, *g1b, *g2b, *gmx, *f1, *f2, *f3;
    int *nidx1, *cnt1, *nidx2, *cnt2;
    cudaGetSymbolAddress((void**)&pool,  g_pool);
    cudaGetSymbolAddress((void**)&pos1,  g_pos1);
    cudaGetSymbolAddress((void**)&pos2,  g_pos2);
    cudaGetSymbolAddress((void**)&nidx1, g_nidx1);
    cudaGetSymbolAddress((void**)&cnt1,  g_cnt1);
    cudaGetSymbolAddress((void**)&nidx2, g_nidx2);
    cudaGetSymbolAddress((void**)&cnt2,  g_cnt2);
    cudaGetSymbolAddress((void**)&x2cat, g_x2cat);
    cudaGetSymbolAddress((void**)&g1b,   g_g1);
    cudaGetSymbolAddress((void**)&g2b,   g_g2);
    cudaGetSymbolAddress((void**)&gmx,   g_gmx);
    cudaGetSymbolAddress((void**)&f1,    g_f1);
    cudaGetSymbolAddress((void**)&f2,    g_f2);
    cudaGetSymbolAddress((void**)&f3,    g_f3);
    float* h2s2 = pool;

    static cudaStream_t sideStream = 0;
    static cudaEvent_t evPos1 = 0, evSide = 0;
    static int attr_done = 0;
    if (!attr_done) {
        cudaFuncSetAttribute(fps_kernel<16>, cudaFuncAttributeMaxDynamicSharedMemorySize, 4096*12 + 128);
        cudaFuncSetAttribute(fps_kernel<8>,  cudaFuncAttributeMaxDynamicSharedMemorySize, 2048*12 + 128);
        cudaFuncSetAttribute(s1_fused,  cudaFuncAttributeMaxDynamicSharedMemorySize, 97280);
        cudaFuncSetAttribute(s2a_fused, cudaFuncAttributeMaxDynamicSharedMemorySize, 216320);
        cudaFuncSetAttribute(s2b_fused, cudaFuncAttributeMaxDynamicSharedMemorySize, 174080);
        cudaStreamCreateWithFlags(&sideStream, cudaStreamNonBlocking);
        cudaEventCreateWithFlags(&evPos1, cudaEventDisableTiming);
        cudaEventCreateWithFlags(&evSide, cudaEventDisableTiming);
        attr_done = 1;
    }

    float r2a = (float)(0.1*0.1), r2b = (float)(0.2*0.2);

    // ---- stage 1 (main stream) ----
    fps_kernel<16><<<8, 256, 4096*12 + 128>>>(pts, pos1, 4096, 2048);
    cudaEventRecord(evPos1, 0);

    // ---- side stream: fps8 + radius2 overlap radius1/s1 ----
    cudaStreamWaitEvent(sideStream, evPos1, 0);
    fps_kernel<8><<<8, 256, 2048*12 + 128, sideStream>>>(pos1, pos2, 2048, 512);
    radius_kernel<<<512, 256, 0, sideStream>>>(pos1, pos2, 2048, 512, r2b, nidx2, cnt2);
    cudaEventRecord(evSide, sideStream);

    // ---- main stream continues ----
    radius_kernel<<<2048, 256>>>(pts, pos1, 4096, 2048, r2a, nidx1, cnt1);
    s1_fused<<<4096, 256, 97280>>>(pts, s1w1, s1b1, s1w2, s1b2, s1w3, s1b3);
    cudaStreamWaitEvent(0, evSide, 0);
    s2a_fused<<<1024, 256, 216320>>>(s2w1, s2b1, s2w2, s2b2, h2s2);
    s2b_fused<<<1024, 256, 174080>>>(h2s2, s2w3, s2b3);

    // ---- global MLP (tf32) + fused pooling + head ----
    gemm_tf32<0><<<dim3(4, 32), 256>>>(x2cat, gw1, gb1, g1b, 4096, 256, 259, 1);
    gemm_tf32<0><<<dim3(8, 32), 256>>>(g1b, gw2, gb2, g2b, 4096, 512, 256, 1);
    gemm_tf32<1><<<dim3(16, 32), 256>>>(g2b, gw3, gb3, gmx, 4096, 1024, 512, 0);
    gemm_tf32<0><<<dim3(8, 1), 256>>>(gmx, l1w, l1b, f1, 128, 512, 1024, 1);
    gemm_tf32<0><<<dim3(4, 1), 256>>>(f1, l2w, l2b, f2, 128, 256, 512, 1);
    gemm_k<<<dim3(1, 1), 256>>>(f2, l3w, l3b, f3, 32, 7, 256, 0);
    final_kernel<<<1, 64>>>((float*)d_out);
}

// round 15
// speedup vs baseline: 1.0502x; 1.0502x over previous
#include <cuda_runtime.h>
#include <math.h>

#define NEGB -1.0e30f

// ----------------- scratch -----------------
__device__ float g_pool[67108864];
__device__ float g_pos1[8*2048*3];
__device__ float g_pos2[8*512*3];
__device__ int   g_nidx1[8*2048*64];
__device__ int   g_cnt1[8*2048];
__device__ int   g_nidx2[8*512*64];
__device__ int   g_cnt2[8*512];
__device__ float g_x1[8*2048*128];
__device__ float g_x2cat[8*512*259];
__device__ float g_g1[8*512*256];
__device__ float g_g2[8*512*512];
__device__ float g_gmx[128*1024];
__device__ float g_f1[128*512];
__device__ float g_f2[128*256];
__device__ float g_f3[32*7];

// ---- packed f32x2 helpers ----
__device__ __forceinline__ unsigned long long pk2(float lo, float hi) {
    unsigned long long r; asm("mov.b64 %0, {%1, %2};" : "=l"(r) : "f"(lo), "f"(hi)); return r;
}
__device__ __forceinline__ void upk2(unsigned long long v, float& lo, float& hi) {
    asm("mov.b64 {%0, %1}, %2;" : "=f"(lo), "=f"(hi) : "l"(v));
}
__device__ __forceinline__ unsigned long long add2(unsigned long long a, unsigned long long b) {
    unsigned long long r; asm("add.rn.f32x2 %0, %1, %2;" : "=l"(r) : "l"(a), "l"(b)); return r;
}
__device__ __forceinline__ unsigned long long mul2(unsigned long long a, unsigned long long b) {
    unsigned long long r; asm("mul.rn.f32x2 %0, %1, %2;" : "=l"(r) : "l"(a), "l"(b)); return r;
}

// ---- tf32 mma helpers ----
__device__ __forceinline__ unsigned f2tf(float f) {
    unsigned r; asm("cvt.rna.tf32.f32 %0, %1;" : "=r"(r) : "f"(f)); return r;
}
__device__ __forceinline__ void mma8(float c[4], unsigned a0, unsigned a1, unsigned a2, unsigned a3,
                                     unsigned b0, unsigned b1) {
    asm volatile("mma.sync.aligned.m16n8k8.row.col.f32.tf32.tf32.f32 "
                 "{%0,%1,%2,%3},{%4,%5,%6,%7},{%8,%9},{%0,%1,%2,%3};"
                 : "+f"(c[0]), "+f"(c[1]), "+f"(c[2]), "+f"(c[3])
                 : "r"(a0), "r"(a1), "r"(a2), "r"(a3), "r"(b0), "r"(b1));
}

// ----------------- FPS (R13 winner: 128 thr, tree bv) -----------------------
template<int PT>
__global__ __launch_bounds__(128) void fps_kernel(const float* __restrict__ posIn,
                                                  float* __restrict__ posOut,
                                                  int N, int S)
{
    extern __shared__ float sm[];
    float* spx = sm;
    float* spy = sm + N;
    float* spz = sm + 2*N;
    unsigned long long* part = (unsigned long long*)(sm + 3*N);

    int b = blockIdx.x, t = threadIdx.x;
    int lane = t & 31, warp = t >> 5;
    const float* p = posIn + (size_t)b*N*3;
    unsigned long long pxp[PT/2], pyp[PT/2], pzp[PT/2];
    float mind[PT];
    #pragma unroll
    for (int jj = 0; jj < PT/2; jj++) {
        int i0 = (2*jj)*128 + t, i1 = (2*jj+1)*128 + t;
        float x0 = p[3*i0], y0 = p[3*i0+1], z0 = p[3*i0+2];
        float x1 = p[3*i1], y1 = p[3*i1+1], z1 = p[3*i1+2];
        spx[i0] = x0; spy[i0] = y0; spz[i0] = z0;
        spx[i1] = x1; spy[i1] = y1; spz[i1] = z1;
        pxp[jj] = pk2(x0, x1); pyp[jj] = pk2(y0, y1); pzp[jj] = pk2(z0, z1);
        mind[2*jj] = 3.402823466e38f; mind[2*jj+1] = 3.402823466e38f;
    }
    if (t == 0) {
        float* o = posOut + (size_t)b*S*3;
        o[0] = p[0]; o[1] = p[1]; o[2] = p[2];
    }
    __syncthreads();
    int bidx = 0;
    for (int s = 1; s < S; s++) {
        float lx = spx[bidx], ly = spy[bidx], lz = spz[bidx];
        unsigned long long nx = pk2(-lx, -lx), ny = pk2(-ly, -ly), nz = pk2(-lz, -lz);
        float bva[4] = {NEGB, NEGB, NEGB, NEGB};
        #pragma unroll
        for (int jj = 0; jj < PT/2; jj++) {
            unsigned long long dx = add2(pxp[jj], nx);
            unsigned long long dy = add2(pyp[jj], ny);
            unsigned long long dz = add2(pzp[jj], nz);
            unsigned long long d2 = add2(add2(mul2(dx,dx), mul2(dy,dy)), mul2(dz,dz));
            float dlo, dhi; upk2(d2, dlo, dhi);
            float m0 = fminf(mind[2*jj],   dlo); mind[2*jj]   = m0;
            float m1 = fminf(mind[2*jj+1], dhi); mind[2*jj+1] = m1;
            bva[jj & 3] = fmaxf(bva[jj & 3], fmaxf(m0, m1));
        }
        float bv = fmaxf(fmaxf(bva[0], bva[1]), fmaxf(bva[2], bva[3]));
        unsigned vb = __float_as_uint(bv);
        unsigned vmax = __reduce_max_sync(0xffffffffu, vb);
        int cand = 0x7fffffff;
        if (vb == vmax) {
            #pragma unroll
            for (int j = PT-1; j >= 0; j--)
                if (__float_as_uint(mind[j]) == vmax) cand = j*128 + t;
        }
        int widx = __reduce_min_sync(0xffffffffu, cand);
        if (lane == 0)
            part[(s & 1)*4 + warp] =
                ((unsigned long long)vmax << 32) | (unsigned)(0xFFFFFFFFu - (unsigned)widx);
        __syncthreads();
        const unsigned long long* pp = part + (s & 1)*4;
        unsigned long long k0 = pp[0], k1 = pp[1], k2 = pp[2], k3 = pp[3];
        k0 = k0 > k1 ? k0 : k1;
        k2 = k2 > k3 ? k2 : k3;
        k0 = k0 > k2 ? k0 : k2;
        bidx = (int)(0xFFFFFFFFu - (unsigned)(k0 & 0xFFFFFFFFu));
        if (t == 0) {
            float* o = posOut + ((size_t)b*S + s)*3;
            o[0] = spx[bidx]; o[1] = spy[bidx]; o[2] = spz[bidx];
        }
    }
}

// ----------------- radius NN v2: smem-staged positions -----------------------
__global__ void radius_kernel(const float* __restrict__ posAll, const float* __restrict__ posQ,
                              int N, int M, float r2,
                              int* __restrict__ nidx, int* __restrict__ cnt)
{
    extern __shared__ float sp[];
    float* spx = sp; float* spy = sp + N; float* spz = sp + 2*N;
    __shared__ unsigned long long cand[8][256];
    __shared__ int scnt[8];
    int warp = threadIdx.x >> 5, lane = threadIdx.x & 31;
    int q = blockIdx.x * 8 + warp;
    int b = q / M;          // all warps in block share b (M % 8 == 0)
    const float* p = posAll + (size_t)b*N*3;
    for (int i = threadIdx.x; i < N; i += 256) {
        spx[i] = p[3*i]; spy[i] = p[3*i+1]; spz[i] = p[3*i+2];
    }
    if (lane == 0) scnt[warp] = 0;
    __syncthreads();
    const float* qp = posQ + (size_t)q*3;
    float qx = qp[0], qy = qp[1], qz = qp[2];
    for (int i = lane; i < N; i += 32) {
        float dx = __fsub_rn(qx, spx[i]);
        float dy = __fsub_rn(qy, spy[i]);
        float dz = __fsub_rn(qz, spz[i]);
        float d2 = __fadd_rn(__fadd_rn(__fmul_rn(dx,dx), __fmul_rn(dy,dy)), __fmul_rn(dz,dz));
        if (d2 <= r2) {
            int pos = atomicAdd(&scnt[warp], 1);
            if (pos < 256)
                cand[warp][pos] = ((unsigned long long)__float_as_uint(d2) << 32) | (unsigned)i;
        }
    }
    __syncwarp();
    int c = scnt[warp]; if (c > 256) c = 256;
    int* out = nidx + (size_t)q*64;
    if (c <= 64) {
        for (int t = lane; t < c; t += 32) out[t] = (int)(cand[warp][t] & 0xffffffffu);
        if (lane == 0) cnt[q] = c;
    } else {
        int slots = (c + 31) >> 5;
        for (int sel = 0; sel < 64; sel++) {
            unsigned long long best = ~0ULL;
            for (int k = 0; k < slots; k++) {
                int j = lane + (k << 5);
                if (j < c) { unsigned long long v = cand[warp][j]; if (v < best) best = v; }
            }
            #pragma unroll
            for (int off = 16; off; off >>= 1) {
                unsigned long long o = __shfl_down_sync(0xffffffffu, best, off);
                if (o < best) best = o;
            }
            best = __shfl_sync(0xffffffffu, best, 0);
            if (lane == 0) out[sel] = (int)(best & 0xffffffffu);
            for (int k = 0; k < slots; k++) {
                int j = lane + (k << 5);
                if (j < c && cand[warp][j] == best) cand[warp][j] = ~0ULL;
            }
        }
        if (lane == 0) cnt[q] = 64;
    }
}

// ============ Stage-1: scalar layer1 + tf32 mma layers 2/3, QPB=4 ============
__global__ __launch_bounds__(256) void s1_fused(const float* __restrict__ pts,
    const float* __restrict__ w1, const float* __restrict__ b1,
    const float* __restrict__ w2, const float* __restrict__ b2,
    const float* __restrict__ w3, const float* __restrict__ b3)
{
    extern __shared__ unsigned usm[];
    unsigned* uW2 = usm;
    unsigned* uW3 = usm + 4608;
    unsigned* uH1 = usm + 13312;
    unsigned* uH2 = usm + 18176;
    float* fW1  = (float*)(usm + 23040);
    float* fB1  = (float*)(usm + 23232);
    float* fB2  = (float*)(usm + 23296);
    float* fB3  = (float*)(usm + 23360);
    float* fRel = (float*)(usm + 23488);
    float* fPart= (float*)(usm + 23744);

    int tid = threadIdx.x;
    int lane = tid & 31, w = tid >> 5;
    int t4 = lane >> 2, tm4 = lane & 3;
    int r0 = (w & 3) * 16;

    for (int i = tid; i < 192;  i += 256) fW1[i] = w1[i];
    for (int i = tid; i < 64;   i += 256) { fB1[i] = b1[i]; fB2[i] = b2[i]; }
    if (tid < 128) fB3[tid] = b3[tid];
    for (int i = tid; i < 4608; i += 256) {
        int k = i / 72, n = i - k*72;
        uW2[i] = (n < 64) ? f2tf(w2[k*64 + n]) : 0u;
    }
    for (int i = tid; i < 8704; i += 256) {
        int k = i / 136, n = i - k*136;
        uW3[i] = (n < 128) ? f2tf(w3[k*128 + n]) : 0u;
    }

    for (int qi = 0; qi < 4; qi++) {
        int q = blockIdx.x*4 + qi;
        int b = q >> 11;
        int cnt = g_cnt1[q];
        if (tid < 64) {
            int idx = (tid < cnt) ? g_nidx1[q*64 + tid] : 0;
            const float* sp = pts + ((size_t)b*4096 + idx)*3;
            const float* qp = g_pos1 + (size_t)q*3;
            fRel[tid*4+0] = sp[0] - qp[0];
            fRel[tid*4+1] = sp[1] - qp[1];
            fRel[tid*4+2] = sp[2] - qp[2];
        }
        __syncthreads();
        {
            int m = tid >> 2, j0 = (tid & 3) * 16;
            float rx = fRel[m*4], ry = fRel[m*4+1], rz = fRel[m*4+2];
            #pragma unroll
            for (int j = 0; j < 16; j++) {
                int c = j0 + j;
                float v = fmaf(rz, fW1[128+c], fmaf(ry, fW1[64+c], fmaf(rx, fW1[c], fB1[c])));
                uH1[m*76 + c] = f2tf(fmaxf(v, 0.f));
            }
        }
        __syncthreads();
        int active = (r0 < cnt);
        if (active) {
            int c0 = (w >> 2) * 32;
            float acc[4][4];
            #pragma unroll
            for (int nt = 0; nt < 4; nt++) { acc[nt][0]=acc[nt][1]=acc[nt][2]=acc[nt][3]=0.f; }
            #pragma unroll
            for (int kk = 0; kk < 64; kk += 8) {
                unsigned a0 = uH1[(r0+t4)*76   + kk + tm4];
                unsigned a1 = uH1[(r0+t4+8)*76 + kk + tm4];
                unsigned a2 = uH1[(r0+t4)*76   + kk + tm4 + 4];
                unsigned a3 = uH1[(r0+t4+8)*76 + kk + tm4 + 4];
                #pragma unroll
                for (int nt = 0; nt < 4; nt++) {
                    int cb = c0 + nt*8 + t4;
                    unsigned bb0 = uW2[(kk+tm4)*72   + cb];
                    unsigned bb1 = uW2[(kk+tm4+4)*72 + cb];
                    mma8(acc[nt], a0, a1, a2, a3, bb0, bb1);
                }
            }
            #pragma unroll
            for (int nt = 0; nt < 4; nt++) {
                int col = c0 + nt*8 + 2*tm4;
                uH2[(r0+t4)*76   + col]   = f2tf(fmaxf(acc[nt][0] + fB2[col],   0.f));
                uH2[(r0+t4)*76   + col+1] = f2tf(fmaxf(acc[nt][1] + fB2[col+1], 0.f));
                uH2[(r0+t4+8)*76 + col]   = f2tf(fmaxf(acc[nt][2] + fB2[col],   0.f));
                uH2[(r0+t4+8)*76 + col+1] = f2tf(fmaxf(acc[nt][3] + fB2[col+1], 0.f));
            }
        }
        __syncthreads();
        if (active) {
            int c0 = (w >> 2) * 64;
            float acc[8][4];
            #pragma unroll
            for (int nt = 0; nt < 8; nt++) { acc[nt][0]=acc[nt][1]=acc[nt][2]=acc[nt][3]=0.f; }
            #pragma unroll
            for (int kk = 0; kk < 64; kk += 8) {
                unsigned a0 = uH2[(r0+t4)*76   + kk + tm4];
                unsigned a1 = uH2[(r0+t4+8)*76 + kk + tm4];
                unsigned a2 = uH2[(r0+t4)*76   + kk + tm4 + 4];
                unsigned a3 = uH2[(r0+t4+8)*76 + kk + tm4 + 4];
                #pragma unroll
                for (int nt = 0; nt < 8; nt++) {
                    int cb = c0 + nt*8 + t4;
                    unsigned bb0 = uW3[(kk+tm4)*136   + cb];
                    unsigned bb1 = uW3[(kk+tm4+4)*136 + cb];
                    mma8(acc[nt], a0, a1, a2, a3, bb0, bb1);
                }
            }
            bool oka = (r0 + t4) < cnt, okb = (r0 + t4 + 8) < cnt;
            #pragma unroll
            for (int nt = 0; nt < 8; nt++) {
                int col = c0 + nt*8 + 2*tm4;
                float m0 = oka ? (acc[nt][0] + fB3[col])   : NEGB;
                float m1 = oka ? (acc[nt][1] + fB3[col+1]) : NEGB;
                if (okb) {
                    m0 = fmaxf(m0, acc[nt][2] + fB3[col]);
                    m1 = fmaxf(m1, acc[nt][3] + fB3[col+1]);
                }
                #pragma unroll
                for (int off = 16; off >= 4; off >>= 1) {
                    m0 = fmaxf(m0, __shfl_xor_sync(0xffffffffu, m0, off));
                    m1 = fmaxf(m1, __shfl_xor_sync(0xffffffffu, m1, off));
                }
                if (t4 == 0) {
                    fPart[(w&3)*128 + col]     = m0;
                    fPart[(w&3)*128 + col + 1] = m1;
                }
            }
        }
        __syncthreads();
        if (tid < 128) {
            int nrt = (cnt + 15) >> 4; if (nrt > 4) nrt = 4;
            float m = NEGB;
            for (int r = 0; r < nrt; r++) m = fmaxf(m, fPart[r*128 + tid]);
            g_x1[(size_t)q*128 + tid] = fmaxf(m, 0.f);
        }
        __syncthreads();
    }
}

// ============ Stage-2 part A: tf32 mma (131->128->128), QPB=4 ================
__global__ __launch_bounds__(256) void s2a_fused(
    const float* __restrict__ w1, const float* __restrict__ b1,
    const float* __restrict__ w2, const float* __restrict__ b2,
    float* __restrict__ h2out)
{
    extern __shared__ unsigned usm[];
    unsigned* uW1 = usm;
    unsigned* uW2 = usm + 18496;
    unsigned* uA  = usm + 35904;
    unsigned* uH1 = usm + 44864;
    float* fb1 = (float*)(usm + 53824);
    float* fb2 = (float*)(usm + 53952);

    int tid = threadIdx.x;
    int lane = tid & 31, w = tid >> 5;
    int t4 = lane >> 2, tm4 = lane & 3;
    int r0 = (w & 3) * 16, c0 = (w >> 2) * 64;

    for (int i = tid; i < 18496; i += 256) {
        int k = i / 136, n = i - k*136;
        uW1[i] = (k < 131 && n < 128) ? f2tf(w1[k*128 + n]) : 0u;
    }
    for (int i = tid; i < 17408; i += 256) {
        int k = i / 136, n = i - k*136;
        uW2[i] = (n < 128) ? f2tf(w2[k*128 + n]) : 0u;
    }
    if (tid < 128) { fb1[tid] = b1[tid]; fb2[tid] = b2[tid]; }

    for (int qi = 0; qi < 4; qi++) {
        int q = blockIdx.x*4 + qi;
        int b = q >> 9;
        int cnt = g_cnt2[q];
        {
            int m = tid >> 2, l4 = tid & 3;
            int idx = (m < cnt) ? g_nidx2[q*64 + m] : 0;
            const float4* src = (const float4*)(g_x1 + ((size_t)b*2048 + idx)*128);
            #pragma unroll
            for (int j = 0; j < 8; j++) {
                float4 v = src[l4*8 + j];
                unsigned* d = uA + m*140 + l4*32 + j*4;
                d[0] = f2tf(v.x); d[1] = f2tf(v.y); d[2] = f2tf(v.z); d[3] = f2tf(v.w);
            }
            if (l4 == 0) {
                const float* ps = g_pos1 + ((size_t)b*2048 + idx)*3;
                const float* pq = g_pos2 + (size_t)q*3;
                uA[m*140+128] = f2tf(ps[0]-pq[0]);
                uA[m*140+129] = f2tf(ps[1]-pq[1]);
                uA[m*140+130] = f2tf(ps[2]-pq[2]);
                #pragma unroll
                for (int z = 131; z < 140; z++) uA[m*140+z] = 0u;
            }
        }
        __syncthreads();
        {
            float C1[8][4];
            #pragma unroll
            for (int nt = 0; nt < 8; nt++) { C1[nt][0]=C1[nt][1]=C1[nt][2]=C1[nt][3]=0.f; }
            for (int ks = 0; ks < 17; ks++) {
                int k0 = ks*8;
                unsigned a0 = uA[(r0+t4)*140   + k0 + tm4];
                unsigned a1 = uA[(r0+t4+8)*140 + k0 + tm4];
                unsigned a2 = uA[(r0+t4)*140   + k0 + tm4 + 4];
                unsigned a3 = uA[(r0+t4+8)*140 + k0 + tm4 + 4];
                #pragma unroll
                for (int nt = 0; nt < 8; nt++) {
                    int cb = c0 + nt*8 + t4;
                    unsigned bb0 = uW1[(k0+tm4)*136   + cb];
                    unsigned bb1 = uW1[(k0+tm4+4)*136 + cb];
                    mma8(C1[nt], a0, a1, a2, a3, bb0, bb1);
                }
            }
            #pragma unroll
            for (int nt = 0; nt < 8; nt++) {
                int col = c0 + nt*8 + 2*tm4;
                uH1[(r0+t4)*140   + col]   = f2tf(fmaxf(C1[nt][0] + fb1[col],   0.f));
                uH1[(r0+t4)*140   + col+1] = f2tf(fmaxf(C1[nt][1] + fb1[col+1], 0.f));
                uH1[(r0+t4+8)*140 + col]   = f2tf(fmaxf(C1[nt][2] + fb1[col],   0.f));
                uH1[(r0+t4+8)*140 + col+1] = f2tf(fmaxf(C1[nt][3] + fb1[col+1], 0.f));
            }
        }
        __syncthreads();
        {
            float C2[8][4];
            #pragma unroll
            for (int nt = 0; nt < 8; nt++) { C2[nt][0]=C2[nt][1]=C2[nt][2]=C2[nt][3]=0.f; }
            for (int ks = 0; ks < 16; ks++) {
                int k0 = ks*8;
                unsigned a0 = uH1[(r0+t4)*140   + k0 + tm4];
                unsigned a1 = uH1[(r0+t4+8)*140 + k0 + tm4];
                unsigned a2 = uH1[(r0+t4)*140   + k0 + tm4 + 4];
                unsigned a3 = uH1[(r0+t4+8)*140 + k0 + tm4 + 4];
                #pragma unroll
                for (int nt = 0; nt < 8; nt++) {
                    int cb = c0 + nt*8 + t4;
                    unsigned bb0 = uW2[(k0+tm4)*136   + cb];
                    unsigned bb1 = uW2[(k0+tm4+4)*136 + cb];
                    mma8(C2[nt], a0, a1, a2, a3, bb0, bb1);
                }
            }
            #pragma unroll
            for (int nt = 0; nt < 8; nt++) {
                int col = c0 + nt*8 + 2*tm4;
                float2 va = make_float2(fmaxf(C2[nt][0] + fb2[col],   0.f),
                                        fmaxf(C2[nt][1] + fb2[col+1], 0.f));
                float2 vb = make_float2(fmaxf(C2[nt][2] + fb2[col],   0.f),
                                        fmaxf(C2[nt][3] + fb2[col+1], 0.f));
                *(float2*)(h2out + ((size_t)q*64 + r0+t4)*128   + col) = va;
                *(float2*)(h2out + ((size_t)q*64 + r0+t4+8)*128 + col) = vb;
            }
        }
        __syncthreads();
    }
}

// ============ Stage-2 part B: tf32 mma + masked max, QPB=4 ===================
__global__ __launch_bounds__(256) void s2b_fused(
    const float* __restrict__ h2, const float* __restrict__ w3, const float* __restrict__ b3)
{
    extern __shared__ unsigned usm[];
    unsigned* uW3 = usm;
    unsigned* uA  = usm + 33792;
    float* fb3   = (float*)(usm + 42240);
    float* sPart = (float*)(usm + 42496);

    int tid = threadIdx.x;
    int lane = tid & 31, w = tid >> 5;
    int t4 = lane >> 2, tm4 = lane & 3;
    int r0 = (w & 3) * 16, c0 = (w >> 2) * 128;

    for (int i = tid; i < 33792; i += 256) {
        int k = i / 264, n = i - k*264;
        uW3[i] = (n < 256) ? f2tf(w3[k*256 + n]) : 0u;
    }
    if (tid < 256) fb3[tid] = b3[tid];

    for (int qi = 0; qi < 4; qi++) {
        int q = blockIdx.x*4 + qi;
        {
            int m = tid >> 2, l4 = tid & 3;
            const float4* src = (const float4*)(h2 + ((size_t)q*64 + m)*128);
            #pragma unroll
            for (int j = 0; j < 8; j++) {
                float4 v = src[l4*8 + j];
                unsigned* d = uA + m*132 + l4*32 + j*4;
                d[0] = f2tf(v.x); d[1] = f2tf(v.y); d[2] = f2tf(v.z); d[3] = f2tf(v.w);
            }
        }
        __syncthreads();
        int cnt = g_cnt2[q];
        float C[16][4];
        #pragma unroll
        for (int nt = 0; nt < 16; nt++) { C[nt][0]=C[nt][1]=C[nt][2]=C[nt][3]=0.f; }
        for (int ks = 0; ks < 16; ks++) {
            int k0 = ks*8;
            unsigned a0 = uA[(r0+t4)*132   + k0 + tm4];
            unsigned a1 = uA[(r0+t4+8)*132 + k0 + tm4];
            unsigned a2 = uA[(r0+t4)*132   + k0 + tm4 + 4];
            unsigned a3 = uA[(r0+t4+8)*132 + k0 + tm4 + 4];
            #pragma unroll
            for (int nt = 0; nt < 16; nt++) {
                int cb = c0 + nt*8 + t4;
                unsigned bb0 = uW3[(k0+tm4)*264   + cb];
                unsigned bb1 = uW3[(k0+tm4+4)*264 + cb];
                mma8(C[nt], a0, a1, a2, a3, bb0, bb1);
            }
        }
        bool oka = (r0 + t4) < cnt, okb = (r0 + t4 + 8) < cnt;
        #pragma unroll
        for (int nt = 0; nt < 16; nt++) {
            int col = c0 + nt*8 + 2*tm4;
            float m0 = oka ? (C[nt][0] + fb3[col])   : NEGB;
            float m1 = oka ? (C[nt][1] + fb3[col+1]) : NEGB;
            if (okb) {
                m0 = fmaxf(m0, C[nt][2] + fb3[col]);
                m1 = fmaxf(m1, C[nt][3] + fb3[col+1]);
            }
            #pragma unroll
            for (int off = 16; off >= 4; off >>= 1) {
                m0 = fmaxf(m0, __shfl_xor_sync(0xffffffffu, m0, off));
                m1 = fmaxf(m1, __shfl_xor_sync(0xffffffffu, m1, off));
            }
            if (t4 == 0) {
                sPart[(w&3)*256 + col]     = m0;
                sPart[(w&3)*256 + col + 1] = m1;
            }
        }
        __syncthreads();
        {
            float m = fmaxf(fmaxf(sPart[tid], sPart[256+tid]),
                            fmaxf(sPart[512+tid], sPart[768+tid]));
            g_x2cat[(size_t)q*259 + tid] = fmaxf(m, 0.f);
            if (tid < 3)
                g_x2cat[(size_t)q*259 + 256 + tid] = g_pos2[(size_t)q*3 + tid];
        }
        __syncthreads();
    }
}

// ============ tf32 GEMM (128x64 tile) with optional fused group-max ==========
template<int GMAX>
__global__ __launch_bounds__(256) void gemm_tf32(const float* __restrict__ A,
    const float* __restrict__ W, const float* __restrict__ bias,
    float* __restrict__ C, int M, int N, int K, int relu)
{
    __shared__ unsigned uA[128*20];
    __shared__ unsigned uW[16*72];
    __shared__ float sPart[4*64];
    int tid = threadIdx.x;
    int lane = tid & 31, w = tid >> 5;
    int t4 = lane >> 2, tm4 = lane & 3;
    int r0 = (w & 3) * 32, c0 = (w >> 2) * 32;
    int row0 = blockIdx.y * 128, col0 = blockIdx.x * 64;

    float acc[2][4][4];
    #pragma unroll
    for (int mt = 0; mt < 2; mt++)
        #pragma unroll
        for (int nt = 0; nt < 4; nt++)
            #pragma unroll
            for (int j = 0; j < 4; j++) acc[mt][nt][j] = 0.f;

    int nk = (K + 15) >> 4;
    for (int ks = 0; ks < nk; ks++) {
        int k0 = ks * 16;
        #pragma unroll
        for (int l = 0; l < 8; l++) {
            int idx = tid + l*256;
            int r = idx >> 4, c = idx & 15;
            int gc = k0 + c;
            uA[r*20 + c] = (gc < K) ? f2tf(A[(size_t)(row0 + r)*K + gc]) : 0u;
        }
        #pragma unroll
        for (int l = 0; l < 4; l++) {
            int idx = tid + l*256;
            int r = idx >> 6, c = idx & 63;
            int gr = k0 + r;
            uW[r*72 + c] = (gr < K) ? f2tf(W[(size_t)gr*N + col0 + c]) : 0u;
        }
        __syncthreads();
        #pragma unroll
        for (int kk = 0; kk < 16; kk += 8) {
            unsigned a0[2], a1[2], a2[2], a3[2];
            #pragma unroll
            for (int mt = 0; mt < 2; mt++) {
                a0[mt] = uA[(r0 + mt*16 + t4)*20   + kk + tm4];
                a1[mt] = uA[(r0 + mt*16 + t4+8)*20 + kk + tm4];
                a2[mt] = uA[(r0 + mt*16 + t4)*20   + kk + tm4 + 4];
                a3[mt] = uA[(r0 + mt*16 + t4+8)*20 + kk + tm4 + 4];
            }
            #pragma unroll
            for (int nt = 0; nt < 4; nt++) {
                int cb = c0 + nt*8 + t4;
                unsigned bb0 = uW[(kk+tm4)*72   + cb];
                unsigned bb1 = uW[(kk+tm4+4)*72 + cb];
                #pragma unroll
                for (int mt = 0; mt < 2; mt++)
                    mma8(acc[mt][nt], a0[mt], a1[mt], a2[mt], a3[mt], bb0, bb1);
            }
        }
        __syncthreads();
    }
    if (GMAX) {
        #pragma unroll
        for (int nt = 0; nt < 4; nt++) {
            int colr = c0 + nt*8 + 2*tm4;
            float bq0 = bias[col0 + colr], bq1 = bias[col0 + colr + 1];
            float m0 = fmaxf(fmaxf(acc[0][nt][0], acc[0][nt][2]),
                             fmaxf(acc[1][nt][0], acc[1][nt][2])) + bq0;
            float m1 = fmaxf(fmaxf(acc[0][nt][1], acc[0][nt][3]),
                             fmaxf(acc[1][nt][1], acc[1][nt][3])) + bq1;
            #pragma unroll
            for (int off = 16; off >= 4; off >>= 1) {
                m0 = fmaxf(m0, __shfl_xor_sync(0xffffffffu, m0, off));
                m1 = fmaxf(m1, __shfl_xor_sync(0xffffffffu, m1, off));
            }
            if (t4 == 0) {
                sPart[(w&3)*64 + colr]     = m0;
                sPart[(w&3)*64 + colr + 1] = m1;
            }
        }
        __syncthreads();
        if (tid < 64) {
            float m = fmaxf(fmaxf(sPart[tid], sPart[64+tid]),
                            fmaxf(sPart[128+tid], sPart[192+tid]));
            C[(size_t)blockIdx.y*1024 + col0 + tid] = m;
        }
    } else {
        #pragma unroll
        for (int mt = 0; mt < 2; mt++) {
            #pragma unroll
            for (int nt = 0; nt < 4; nt++) {
                int gc = col0 + c0 + nt*8 + 2*tm4;
                float v0 = acc[mt][nt][0] + bias[gc];
                float v1 = acc[mt][nt][1] + bias[gc+1];
                float v2 = acc[mt][nt][2] + bias[gc];
                float v3 = acc[mt][nt][3] + bias[gc+1];
                if (relu) {
                    v0 = fmaxf(v0, 0.f); v1 = fmaxf(v1, 0.f);
                    v2 = fmaxf(v2, 0.f); v3 = fmaxf(v3, 0.f);
                }
                int gr = row0 + r0 + mt*16 + t4;
                *(float2*)(C + (size_t)gr*N + gc)     = make_float2(v0, v1);
                *(float2*)(C + (size_t)(gr+8)*N + gc) = make_float2(v2, v3);
            }
        }
    }
}

// ----------------- fused head: f2 @ l3w + b, mean, quat-normalize -------------
__global__ void headfinal_kernel(const float* __restrict__ l3w, const float* __restrict__ l3b,
                                 float* __restrict__ out)
{
    __shared__ float sf3[32*7];
    __shared__ float sm[8][7];
    int t = threadIdx.x;
    if (t < 224) {
        int row = t / 7, col = t % 7;
        const float* a = g_f2 + (size_t)row*256;
        float s = 0.f;
        for (int k = 0; k < 256; k++) s = fmaf(a[k], l3w[k*7 + col], s);
        sf3[row*7 + col] = s + l3b[col];
    }
    __syncthreads();
    if (t < 56) {
        int b = t / 7, c = t % 7;
        float s = sf3[(b*4)*7+c] + sf3[(b*4+1)*7+c] + sf3[(b*4+2)*7+c] + sf3[(b*4+3)*7+c];
        sm[b][c] = s * 0.25f;
    }
    __syncthreads();
    if (t < 8) {
        float q0 = sm[t][3], q1 = sm[t][4], q2 = sm[t][5], q3 = sm[t][6];
        float nrm = sqrtf(q0*q0 + q1*q1 + q2*q2 + q3*q3);
        float d = fmaxf(nrm, 1e-12f);
        out[t*7+0] = sm[t][0]; out[t*7+1] = sm[t][1]; out[t*7+2] = sm[t][2];
        out[t*7+3] = q0/d; out[t*7+4] = q1/d; out[t*7+5] = q2/d; out[t*7+6] = q3/d;
    }
}

// ----------------- launcher --------------------------------------------------
extern "C" void kernel_launch(void* const* d_in, const int* in_sizes, int n_in,
                              void* d_out, int out_size)
{
    const float* pts  = (const float*)d_in[0];
    const float *s1w1 = (const float*)d_in[1],  *s1b1 = (const float*)d_in[2];
    const float *s1w2 = (const float*)d_in[3],  *s1b2 = (const float*)d_in[4];
    const float *s1w3 = (const float*)d_in[5],  *s1b3 = (const float*)d_in[6];
    const float *s2w1 = (const float*)d_in[7],  *s2b1 = (const float*)d_in[8];
    const float *s2w2 = (const float*)d_in[9],  *s2b2 = (const float*)d_in[10];
    const float *s2w3 = (const float*)d_in[11], *s2b3 = (const float*)d_in[12];
    const float *gw1  = (const float*)d_in[13], *gb1  = (const float*)d_in[14];
    const float *gw2  = (const float*)d_in[15], *gb2  = (const float*)d_in[16];
    const float *gw3  = (const float*)d_in[17], *gb3  = (const float*)d_in[18];
    const float *l1w  = (const float*)d_in[19], *l1b  = (const float*)d_in[20];
    const float *l2w  = (const float*)d_in[21], *l2b  = (const float*)d_in[22];
    const float *l3w  = (const float*)d_in[23], *l3b  = (const float*)d_in[24];

    float *pool, *pos1, *pos2, *x2cat, *g1b, *g2b, *gmx, *f1, *f2;
    int *nidx1, *cnt1, *nidx2, *cnt2;
    cudaGetSymbolAddress((void**)&pool,  g_pool);
    cudaGetSymbolAddress((void**)&pos1,  g_pos1);
    cudaGetSymbolAddress((void**)&pos2,  g_pos2);
    cudaGetSymbolAddress((void**)&nidx1, g_nidx1);
    cudaGetSymbolAddress((void**)&cnt1,  g_cnt1);
    cudaGetSymbolAddress((void**)&nidx2, g_nidx2);
    cudaGetSymbolAddress((void**)&cnt2,  g_cnt2);
    cudaGetSymbolAddress((void**)&x2cat, g_x2cat);
    cudaGetSymbolAddress((void**)&g1b,   g_g1);
    cudaGetSymbolAddress((void**)&g2b,   g_g2);
    cudaGetSymbolAddress((void**)&gmx,   g_gmx);
    cudaGetSymbolAddress((void**)&f1,    g_f1);
    cudaGetSymbolAddress((void**)&f2,    g_f2);
    float* h2s2 = pool;

    static cudaStream_t sideStream = 0;
    static cudaEvent_t evPos1 = 0, evSide = 0;
    static int attr_done = 0;
    if (!attr_done) {
        cudaFuncSetAttribute(fps_kernel<32>, cudaFuncAttributeMaxDynamicSharedMemorySize, 4096*12 + 64);
        cudaFuncSetAttribute(fps_kernel<16>, cudaFuncAttributeMaxDynamicSharedMemorySize, 2048*12 + 64);
        cudaFuncSetAttribute(radius_kernel, cudaFuncAttributeMaxDynamicSharedMemorySize, 49152);
        cudaFuncSetAttribute(s1_fused,  cudaFuncAttributeMaxDynamicSharedMemorySize, 97280);
        cudaFuncSetAttribute(s2a_fused, cudaFuncAttributeMaxDynamicSharedMemorySize, 216320);
        cudaFuncSetAttribute(s2b_fused, cudaFuncAttributeMaxDynamicSharedMemorySize, 174080);
        cudaStreamCreateWithFlags(&sideStream, cudaStreamNonBlocking);
        cudaEventCreateWithFlags(&evPos1, cudaEventDisableTiming);
        cudaEventCreateWithFlags(&evSide, cudaEventDisableTiming);
        attr_done = 1;
    }

    float r2a = (float)(0.1*0.1), r2b = (float)(0.2*0.2);

    // ---- stage 1 (main stream) ----
    fps_kernel<32><<<8, 128, 4096*12 + 64>>>(pts, pos1, 4096, 2048);
    cudaEventRecord(evPos1, 0);

    // ---- side stream: fps16 + radius2 overlap radius1/s1 ----
    cudaStreamWaitEvent(sideStream, evPos1, 0);
    fps_kernel<16><<<8, 128, 2048*12 + 64, sideStream>>>(pos1, pos2, 2048, 512);
    radius_kernel<<<512, 256, 2048*12, sideStream>>>(pos1, pos2, 2048, 512, r2b, nidx2, cnt2);
    cudaEventRecord(evSide, sideStream);

    // ---- main stream continues ----
    radius_kernel<<<2048, 256, 4096*12>>>(pts, pos1, 4096, 2048, r2a, nidx1, cnt1);
    s1_fused<<<4096, 256, 97280>>>(pts, s1w1, s1b1, s1w2, s1b2, s1w3, s1b3);
    cudaStreamWaitEvent(0, evSide, 0);
    s2a_fused<<<1024, 256, 216320>>>(s2w1, s2b1, s2w2, s2b2, h2s2);
    s2b_fused<<<1024, 256, 174080>>>(h2s2, s2w3, s2b3);

    // ---- global MLP (tf32) + fused pooling + head ----
    gemm_tf32<0><<<dim3(4, 32), 256>>>(x2cat, gw1, gb1, g1b, 4096, 256, 259, 1);
    gemm_tf32<0><<<dim3(8, 32), 256>>>(g1b, gw2, gb2, g2b, 4096, 512, 256, 1);
    gemm_tf32<1><<<dim3(16, 32), 256>>>(g2b, gw3, gb3, gmx, 4096, 1024, 512, 0);
    gemm_tf32<0><<<dim3(8, 1), 256>>>(gmx, l1w, l1b, f1, 128, 512, 1024, 1);
    gemm_tf32<0><<<dim3(4, 1), 256>>>(f1, l2w, l2b, f2, 128, 256, 512, 1);
    headfinal_kernel<<<1, 256>>>(l3w, l3b, (float*)d_out);
}

// round 16
// speedup vs baseline: 1.2139x; 1.1559x over previous
#include <cuda_runtime.h>
#include <math.h>

#define NEGB -1.0e30f

// ----------------- scratch -----------------
__device__ float g_pool[67108864];
__device__ float g_pos1[8*2048*3];
__device__ float g_pos2[8*512*3];
__device__ int   g_nidx1[8*2048*64];
__device__ int   g_cnt1[8*2048];
__device__ int   g_nidx2[8*512*64];
__device__ int   g_cnt2[8*512];
__device__ float g_x1[8*2048*128];
__device__ float g_x2cat[8*512*259];
__device__ float g_g1[8*512*256];
__device__ float g_g2[8*512*512];
__device__ float g_gmx[128*1024];
__device__ float g_f1[128*512];
__device__ float g_f2[128*256];
__device__ float g_mind[8*4096];
__device__ int   g_bidx[8];

// ---- packed f32x2 helpers ----
__device__ __forceinline__ unsigned long long pk2(float lo, float hi) {
    unsigned long long r; asm("mov.b64 %0, {%1, %2};" : "=l"(r) : "f"(lo), "f"(hi)); return r;
}
__device__ __forceinline__ void upk2(unsigned long long v, float& lo, float& hi) {
    asm("mov.b64 {%0, %1}, %2;" : "=f"(lo), "=f"(hi) : "l"(v));
}
__device__ __forceinline__ unsigned long long add2(unsigned long long a, unsigned long long b) {
    unsigned long long r; asm("add.rn.f32x2 %0, %1, %2;" : "=l"(r) : "l"(a), "l"(b)); return r;
}
__device__ __forceinline__ unsigned long long mul2(unsigned long long a, unsigned long long b) {
    unsigned long long r; asm("mul.rn.f32x2 %0, %1, %2;" : "=l"(r) : "l"(a), "l"(b)); return r;
}

// ---- tf32 mma helpers ----
__device__ __forceinline__ unsigned f2tf(float f) {
    unsigned r; asm("cvt.rna.tf32.f32 %0, %1;" : "=r"(r) : "f"(f)); return r;
}
__device__ __forceinline__ void mma8(float c[4], unsigned a0, unsigned a1, unsigned a2, unsigned a3,
                                     unsigned b0, unsigned b1) {
    asm volatile("mma.sync.aligned.m16n8k8.row.col.f32.tf32.tf32.f32 "
                 "{%0,%1,%2,%3},{%4,%5,%6,%7},{%8,%9},{%0,%1,%2,%3};"
                 : "+f"(c[0]), "+f"(c[1]), "+f"(c[2]), "+f"(c[3])
                 : "r"(a0), "r"(a1), "r"(a2), "r"(a3), "r"(b0), "r"(b1));
}

// ----------------- FPS chunked (state carried in g_mind/g_bidx) --------------
template<int PT>
__global__ __launch_bounds__(128) void fps_kernel(const float* __restrict__ posIn,
                                                  float* __restrict__ posOut,
                                                  int N, int s0, int s1e)
{
    extern __shared__ float sm[];
    float* spx = sm;
    float* spy = sm + N;
    float* spz = sm + 2*N;
    unsigned long long* part = (unsigned long long*)(sm + 3*N);

    int b = blockIdx.x, t = threadIdx.x;
    int lane = t & 31, warp = t >> 5;
    const float* p = posIn + (size_t)b*N*3;
    unsigned long long pxp[PT/2], pyp[PT/2], pzp[PT/2];
    float mind[PT];
    #pragma unroll
    for (int jj = 0; jj < PT/2; jj++) {
        int i0 = (2*jj)*128 + t, i1 = (2*jj+1)*128 + t;
        float x0 = p[3*i0], y0 = p[3*i0+1], z0 = p[3*i0+2];
        float x1 = p[3*i1], y1 = p[3*i1+1], z1 = p[3*i1+2];
        spx[i0] = x0; spy[i0] = y0; spz[i0] = z0;
        spx[i1] = x1; spy[i1] = y1; spz[i1] = z1;
        pxp[jj] = pk2(x0, x1); pyp[jj] = pk2(y0, y1); pzp[jj] = pk2(z0, z1);
    }
    if (s0 == 0) {
        #pragma unroll
        for (int j = 0; j < PT; j++) mind[j] = 3.402823466e38f;
        if (t == 0) {
            float* o = posOut + (size_t)b*N/ (N/ ( (N>2048)?2:4) )*0; // dummy no-op avoided below
        }
    } else {
        #pragma unroll
        for (int j = 0; j < PT; j++) mind[j] = g_mind[(size_t)b*N + j*128 + t];
    }
    if (s0 == 0 && t == 0) {
        // S = number of output rows; caller guarantees posOut row stride 3
        float* o = posOut + (size_t)b * ((N == 4096) ? 2048 : 512) * 3;
        o[0] = p[0]; o[1] = p[1]; o[2] = p[2];
    }
    __syncthreads();
    int bidx = (s0 == 0) ? 0 : g_bidx[b];
    int S = (N == 4096) ? 2048 : 512;
    for (int s = (s0 == 0 ? 1 : s0); s < s1e; s++) {
        float lx = spx[bidx], ly = spy[bidx], lz = spz[bidx];
        unsigned long long nx = pk2(-lx, -lx), ny = pk2(-ly, -ly), nz = pk2(-lz, -lz);
        float bva[4] = {NEGB, NEGB, NEGB, NEGB};
        #pragma unroll
        for (int jj = 0; jj < PT/2; jj++) {
            unsigned long long dx = add2(pxp[jj], nx);
            unsigned long long dy = add2(pyp[jj], ny);
            unsigned long long dz = add2(pzp[jj], nz);
            unsigned long long d2 = add2(add2(mul2(dx,dx), mul2(dy,dy)), mul2(dz,dz));
            float dlo, dhi; upk2(d2, dlo, dhi);
            float m0 = fminf(mind[2*jj],   dlo); mind[2*jj]   = m0;
            float m1 = fminf(mind[2*jj+1], dhi); mind[2*jj+1] = m1;
            bva[jj & 3] = fmaxf(bva[jj & 3], fmaxf(m0, m1));
        }
        float bv = fmaxf(fmaxf(bva[0], bva[1]), fmaxf(bva[2], bva[3]));
        unsigned vb = __float_as_uint(bv);
        unsigned vmax = __reduce_max_sync(0xffffffffu, vb);
        int cand = 0x7fffffff;
        if (vb == vmax) {
            #pragma unroll
            for (int j = PT-1; j >= 0; j--)
                if (__float_as_uint(mind[j]) == vmax) cand = j*128 + t;
        }
        int widx = __reduce_min_sync(0xffffffffu, cand);
        if (lane == 0)
            part[(s & 1)*4 + warp] =
                ((unsigned long long)vmax << 32) | (unsigned)(0xFFFFFFFFu - (unsigned)widx);
        __syncthreads();
        const unsigned long long* pp = part + (s & 1)*4;
        unsigned long long k0 = pp[0], k1 = pp[1], k2 = pp[2], k3 = pp[3];
        k0 = k0 > k1 ? k0 : k1;
        k2 = k2 > k3 ? k2 : k3;
        k0 = k0 > k2 ? k0 : k2;
        bidx = (int)(0xFFFFFFFFu - (unsigned)(k0 & 0xFFFFFFFFu));
        if (t == 0) {
            float* o = posOut + ((size_t)b*S + s)*3;
            o[0] = spx[bidx]; o[1] = spy[bidx]; o[2] = spz[bidx];
        }
    }
    if (s1e < S) {
        #pragma unroll
        for (int j = 0; j < PT; j++) g_mind[(size_t)b*N + j*128 + t] = mind[j];
        if (t == 0) g_bidx[b] = bidx;
    }
}

// ----------------- radius NN (R13 version + chunk mapping) -------------------
__global__ void radius_kernel(const float* __restrict__ posAll, const float* __restrict__ posQ,
                              int N, int M, float r2,
                              int* __restrict__ nidx, int* __restrict__ cnt,
                              int sOff, int chunkS)
{
    __shared__ unsigned long long cand[8][256];
    __shared__ int scnt[8];
    int warp = threadIdx.x >> 5, lane = threadIdx.x & 31;
    int qLocal = blockIdx.x * 8 + warp;
    int b = qLocal / chunkS;
    int q = b*M + sOff + (qLocal - b*chunkS);
    if (lane == 0) scnt[warp] = 0;
    __syncwarp();
    const float* qp = posQ + (size_t)q*3;
    float qx = qp[0], qy = qp[1], qz = qp[2];
    const float* p = posAll + (size_t)b*N*3;
    for (int i = lane; i < N; i += 32) {
        float dx = __fsub_rn(qx, p[3*i]);
        float dy = __fsub_rn(qy, p[3*i+1]);
        float dz = __fsub_rn(qz, p[3*i+2]);
        float d2 = __fadd_rn(__fadd_rn(__fmul_rn(dx,dx), __fmul_rn(dy,dy)), __fmul_rn(dz,dz));
        if (d2 <= r2) {
            int pos = atomicAdd(&scnt[warp], 1);
            if (pos < 256)
                cand[warp][pos] = ((unsigned long long)__float_as_uint(d2) << 32) | (unsigned)i;
        }
    }
    __syncwarp();
    int c = scnt[warp]; if (c > 256) c = 256;
    int* out = nidx + (size_t)q*64;
    if (c <= 64) {
        for (int t = lane; t < c; t += 32) out[t] = (int)(cand[warp][t] & 0xffffffffu);
        if (lane == 0) cnt[q] = c;
    } else {
        int slots = (c + 31) >> 5;
        for (int sel = 0; sel < 64; sel++) {
            unsigned long long best = ~0ULL;
            for (int k = 0; k < slots; k++) {
                int j = lane + (k << 5);
                if (j < c) { unsigned long long v = cand[warp][j]; if (v < best) best = v; }
            }
            #pragma unroll
            for (int off = 16; off; off >>= 1) {
                unsigned long long o = __shfl_down_sync(0xffffffffu, best, off);
                if (o < best) best = o;
            }
            best = __shfl_sync(0xffffffffu, best, 0);
            if (lane == 0) out[sel] = (int)(best & 0xffffffffu);
            for (int k = 0; k < slots; k++) {
                int j = lane + (k << 5);
                if (j < c && cand[warp][j] == best) cand[warp][j] = ~0ULL;
            }
        }
        if (lane == 0) cnt[q] = 64;
    }
}

// ============ Stage-1: scalar layer1 + tf32 mma layers 2/3, QPB=4, chunked ===
__global__ __launch_bounds__(256) void s1_fused(const float* __restrict__ pts,
    const float* __restrict__ w1, const float* __restrict__ b1,
    const float* __restrict__ w2, const float* __restrict__ b2,
    const float* __restrict__ w3, const float* __restrict__ b3, int sOff)
{
    extern __shared__ unsigned usm[];
    unsigned* uW2 = usm;
    unsigned* uW3 = usm + 4608;
    unsigned* uH1 = usm + 13312;
    unsigned* uH2 = usm + 18176;
    float* fW1  = (float*)(usm + 23040);
    float* fB1  = (float*)(usm + 23232);
    float* fB2  = (float*)(usm + 23296);
    float* fB3  = (float*)(usm + 23360);
    float* fRel = (float*)(usm + 23488);
    float* fPart= (float*)(usm + 23744);

    int tid = threadIdx.x;
    int lane = tid & 31, w = tid >> 5;
    int t4 = lane >> 2, tm4 = lane & 3;
    int r0 = (w & 3) * 16;

    for (int i = tid; i < 192;  i += 256) fW1[i] = w1[i];
    for (int i = tid; i < 64;   i += 256) { fB1[i] = b1[i]; fB2[i] = b2[i]; }
    if (tid < 128) fB3[tid] = b3[tid];
    for (int i = tid; i < 4608; i += 256) {
        int k = i / 72, n = i - k*72;
        uW2[i] = (n < 64) ? f2tf(w2[k*64 + n]) : 0u;
    }
    for (int i = tid; i < 8704; i += 256) {
        int k = i / 136, n = i - k*136;
        uW3[i] = (n < 128) ? f2tf(w3[k*128 + n]) : 0u;
    }

    for (int qi = 0; qi < 4; qi++) {
        int qLocal = blockIdx.x*4 + qi;           // 0..4095 per chunk
        int b = qLocal >> 9;
        int q = b*2048 + sOff + (qLocal & 511);
        int cnt = g_cnt1[q];
        if (tid < 64) {
            int idx = (tid < cnt) ? g_nidx1[q*64 + tid] : 0;
            const float* sp = pts + ((size_t)b*4096 + idx)*3;
            const float* qp = g_pos1 + (size_t)q*3;
            fRel[tid*4+0] = sp[0] - qp[0];
            fRel[tid*4+1] = sp[1] - qp[1];
            fRel[tid*4+2] = sp[2] - qp[2];
        }
        __syncthreads();
        {
            int m = tid >> 2, j0 = (tid & 3) * 16;
            float rx = fRel[m*4], ry = fRel[m*4+1], rz = fRel[m*4+2];
            #pragma unroll
            for (int j = 0; j < 16; j++) {
                int c = j0 + j;
                float v = fmaf(rz, fW1[128+c], fmaf(ry, fW1[64+c], fmaf(rx, fW1[c], fB1[c])));
                uH1[m*76 + c] = f2tf(fmaxf(v, 0.f));
            }
        }
        __syncthreads();
        int active = (r0 < cnt);
        if (active) {
            int c0 = (w >> 2) * 32;
            float acc[4][4];
            #pragma unroll
            for (int nt = 0; nt < 4; nt++) { acc[nt][0]=acc[nt][1]=acc[nt][2]=acc[nt][3]=0.f; }
            #pragma unroll
            for (int kk = 0; kk < 64; kk += 8) {
                unsigned a0 = uH1[(r0+t4)*76   + kk + tm4];
                unsigned a1 = uH1[(r0+t4+8)*76 + kk + tm4];
                unsigned a2 = uH1[(r0+t4)*76   + kk + tm4 + 4];
                unsigned a3 = uH1[(r0+t4+8)*76 + kk + tm4 + 4];
                #pragma unroll
                for (int nt = 0; nt < 4; nt++) {
                    int cb = c0 + nt*8 + t4;
                    unsigned bb0 = uW2[(kk+tm4)*72   + cb];
                    unsigned bb1 = uW2[(kk+tm4+4)*72 + cb];
                    mma8(acc[nt], a0, a1, a2, a3, bb0, bb1);
                }
            }
            #pragma unroll
            for (int nt = 0; nt < 4; nt++) {
                int col = c0 + nt*8 + 2*tm4;
                uH2[(r0+t4)*76   + col]   = f2tf(fmaxf(acc[nt][0] + fB2[col],   0.f));
                uH2[(r0+t4)*76   + col+1] = f2tf(fmaxf(acc[nt][1] + fB2[col+1], 0.f));
                uH2[(r0+t4+8)*76 + col]   = f2tf(fmaxf(acc[nt][2] + fB2[col],   0.f));
                uH2[(r0+t4+8)*76 + col+1] = f2tf(fmaxf(acc[nt][3] + fB2[col+1], 0.f));
            }
        }
        __syncthreads();
        if (active) {
            int c0 = (w >> 2) * 64;
            float acc[8][4];
            #pragma unroll
            for (int nt = 0; nt < 8; nt++) { acc[nt][0]=acc[nt][1]=acc[nt][2]=acc[nt][3]=0.f; }
            #pragma unroll
            for (int kk = 0; kk < 64; kk += 8) {
                unsigned a0 = uH2[(r0+t4)*76   + kk + tm4];
                unsigned a1 = uH2[(r0+t4+8)*76 + kk + tm4];
                unsigned a2 = uH2[(r0+t4)*76   + kk + tm4 + 4];
                unsigned a3 = uH2[(r0+t4+8)*76 + kk + tm4 + 4];
                #pragma unroll
                for (int nt = 0; nt < 8; nt++) {
                    int cb = c0 + nt*8 + t4;
                    unsigned bb0 = uW3[(kk+tm4)*136   + cb];
                    unsigned bb1 = uW3[(kk+tm4+4)*136 + cb];
                    mma8(acc[nt], a0, a1, a2, a3, bb0, bb1);
                }
            }
            bool oka = (r0 + t4) < cnt, okb = (r0 + t4 + 8) < cnt;
            #pragma unroll
            for (int nt = 0; nt < 8; nt++) {
                int col = c0 + nt*8 + 2*tm4;
                float m0 = oka ? (acc[nt][0] + fB3[col])   : NEGB;
                float m1 = oka ? (acc[nt][1] + fB3[col+1]) : NEGB;
                if (okb) {
                    m0 = fmaxf(m0, acc[nt][2] + fB3[col]);
                    m1 = fmaxf(m1, acc[nt][3] + fB3[col+1]);
                }
                #pragma unroll
                for (int off = 16; off >= 4; off >>= 1) {
                    m0 = fmaxf(m0, __shfl_xor_sync(0xffffffffu, m0, off));
                    m1 = fmaxf(m1, __shfl_xor_sync(0xffffffffu, m1, off));
                }
                if (t4 == 0) {
                    fPart[(w&3)*128 + col]     = m0;
                    fPart[(w&3)*128 + col + 1] = m1;
                }
            }
        }
        __syncthreads();
        if (tid < 128) {
            int nrt = (cnt + 15) >> 4; if (nrt > 4) nrt = 4;
            float m = NEGB;
            for (int r = 0; r < nrt; r++) m = fmaxf(m, fPart[r*128 + tid]);
            g_x1[(size_t)q*128 + tid] = fmaxf(m, 0.f);
        }
        __syncthreads();
    }
}

// ============ Stage-2 part A: tf32 mma (131->128->128), QPB=4 ================
__global__ __launch_bounds__(256) void s2a_fused(
    const float* __restrict__ w1, const float* __restrict__ b1,
    const float* __restrict__ w2, const float* __restrict__ b2,
    float* __restrict__ h2out)
{
    extern __shared__ unsigned usm[];
    unsigned* uW1 = usm;
    unsigned* uW2 = usm + 18496;
    unsigned* uA  = usm + 35904;
    unsigned* uH1 = usm + 44864;
    float* fb1 = (float*)(usm + 53824);
    float* fb2 = (float*)(usm + 53952);

    int tid = threadIdx.x;
    int lane = tid & 31, w = tid >> 5;
    int t4 = lane >> 2, tm4 = lane & 3;
    int r0 = (w & 3) * 16, c0 = (w >> 2) * 64;

    for (int i = tid; i < 18496; i += 256) {
        int k = i / 136, n = i - k*136;
        uW1[i] = (k < 131 && n < 128) ? f2tf(w1[k*128 + n]) : 0u;
    }
    for (int i = tid; i < 17408; i += 256) {
        int k = i / 136, n = i - k*136;
        uW2[i] = (n < 128) ? f2tf(w2[k*128 + n]) : 0u;
    }
    if (tid < 128) { fb1[tid] = b1[tid]; fb2[tid] = b2[tid]; }

    for (int qi = 0; qi < 4; qi++) {
        int q = blockIdx.x*4 + qi;
        int b = q >> 9;
        int cnt = g_cnt2[q];
        {
            int m = tid >> 2, l4 = tid & 3;
            int idx = (m < cnt) ? g_nidx2[q*64 + m] : 0;
            const float4* src = (const float4*)(g_x1 + ((size_t)b*2048 + idx)*128);
            #pragma unroll
            for (int j = 0; j < 8; j++) {
                float4 v = src[l4*8 + j];
                unsigned* d = uA + m*140 + l4*32 + j*4;
                d[0] = f2tf(v.x); d[1] = f2tf(v.y); d[2] = f2tf(v.z); d[3] = f2tf(v.w);
            }
            if (l4 == 0) {
                const float* ps = g_pos1 + ((size_t)b*2048 + idx)*3;
                const float* pq = g_pos2 + (size_t)q*3;
                uA[m*140+128] = f2tf(ps[0]-pq[0]);
                uA[m*140+129] = f2tf(ps[1]-pq[1]);
                uA[m*140+130] = f2tf(ps[2]-pq[2]);
                #pragma unroll
                for (int z = 131; z < 140; z++) uA[m*140+z] = 0u;
            }
        }
        __syncthreads();
        {
            float C1[8][4];
            #pragma unroll
            for (int nt = 0; nt < 8; nt++) { C1[nt][0]=C1[nt][1]=C1[nt][2]=C1[nt][3]=0.f; }
            for (int ks = 0; ks < 17; ks++) {
                int k0 = ks*8;
                unsigned a0 = uA[(r0+t4)*140   + k0 + tm4];
                unsigned a1 = uA[(r0+t4+8)*140 + k0 + tm4];
                unsigned a2 = uA[(r0+t4)*140   + k0 + tm4 + 4];
                unsigned a3 = uA[(r0+t4+8)*140 + k0 + tm4 + 4];
                #pragma unroll
                for (int nt = 0; nt < 8; nt++) {
                    int cb = c0 + nt*8 + t4;
                    unsigned bb0 = uW1[(k0+tm4)*136   + cb];
                    unsigned bb1 = uW1[(k0+tm4+4)*136 + cb];
                    mma8(C1[nt], a0, a1, a2, a3, bb0, bb1);
                }
            }
            #pragma unroll
            for (int nt = 0; nt < 8; nt++) {
                int col = c0 + nt*8 + 2*tm4;
                uH1[(r0+t4)*140   + col]   = f2tf(fmaxf(C1[nt][0] + fb1[col],   0.f));
                uH1[(r0+t4)*140   + col+1] = f2tf(fmaxf(C1[nt][1] + fb1[col+1], 0.f));
                uH1[(r0+t4+8)*140 + col]   = f2tf(fmaxf(C1[nt][2] + fb1[col],   0.f));
                uH1[(r0+t4+8)*140 + col+1] = f2tf(fmaxf(C1[nt][3] + fb1[col+1], 0.f));
            }
        }
        __syncthreads();
        {
            float C2[8][4];
            #pragma unroll
            for (int nt = 0; nt < 8; nt++) { C2[nt][0]=C2[nt][1]=C2[nt][2]=C2[nt][3]=0.f; }
            for (int ks = 0; ks < 16; ks++) {
                int k0 = ks*8;
                unsigned a0 = uH1[(r0+t4)*140   + k0 + tm4];
                unsigned a1 = uH1[(r0+t4+8)*140 + k0 + tm4];
                unsigned a2 = uH1[(r0+t4)*140   + k0 + tm4 + 4];
                unsigned a3 = uH1[(r0+t4+8)*140 + k0 + tm4 + 4];
                #pragma unroll
                for (int nt = 0; nt < 8; nt++) {
                    int cb = c0 + nt*8 + t4;
                    unsigned bb0 = uW2[(k0+tm4)*136   + cb];
                    unsigned bb1 = uW2[(k0+tm4+4)*136 + cb];
                    mma8(C2[nt], a0, a1, a2, a3, bb0, bb1);
                }
            }
            #pragma unroll
            for (int nt = 0; nt < 8; nt++) {
                int col = c0 + nt*8 + 2*tm4;
                float2 va = make_float2(fmaxf(C2[nt][0] + fb2[col],   0.f),
                                        fmaxf(C2[nt][1] + fb2[col+1], 0.f));
                float2 vb = make_float2(fmaxf(C2[nt][2] + fb2[col],   0.f),
                                        fmaxf(C2[nt][3] + fb2[col+1], 0.f));
                *(float2*)(h2out + ((size_t)q*64 + r0+t4)*128   + col) = va;
                *(float2*)(h2out + ((size_t)q*64 + r0+t4+8)*128 + col) = vb;
            }
        }
        __syncthreads();
    }
}

// ============ Stage-2 part B: tf32 mma + masked max, QPB=4 ===================
__global__ __launch_bounds__(256) void s2b_fused(
    const float* __restrict__ h2, const float* __restrict__ w3, const float* __restrict__ b3)
{
    extern __shared__ unsigned usm[];
    unsigned* uW3 = usm;
    unsigned* uA  = usm + 33792;
    float* fb3   = (float*)(usm + 42240);
    float* sPart = (float*)(usm + 42496);

    int tid = threadIdx.x;
    int lane = tid & 31, w = tid >> 5;
    int t4 = lane >> 2, tm4 = lane & 3;
    int r0 = (w & 3) * 16, c0 = (w >> 2) * 128;

    for (int i = tid; i < 33792; i += 256) {
        int k = i / 264, n = i - k*264;
        uW3[i] = (n < 256) ? f2tf(w3[k*256 + n]) : 0u;
    }
    if (tid < 256) fb3[tid] = b3[tid];

    for (int qi = 0; qi < 4; qi++) {
        int q = blockIdx.x*4 + qi;
        {
            int m = tid >> 2, l4 = tid & 3;
            const float4* src = (const float4*)(h2 + ((size_t)q*64 + m)*128);
            #pragma unroll
            for (int j = 0; j < 8; j++) {
                float4 v = src[l4*8 + j];
                unsigned* d = uA + m*132 + l4*32 + j*4;
                d[0] = f2tf(v.x); d[1] = f2tf(v.y); d[2] = f2tf(v.z); d[3] = f2tf(v.w);
            }
        }
        __syncthreads();
        int cnt = g_cnt2[q];
        float C[16][4];
        #pragma unroll
        for (int nt = 0; nt < 16; nt++) { C[nt][0]=C[nt][1]=C[nt][2]=C[nt][3]=0.f; }
        for (int ks = 0; ks < 16; ks++) {
            int k0 = ks*8;
            unsigned a0 = uA[(r0+t4)*132   + k0 + tm4];
            unsigned a1 = uA[(r0+t4+8)*132 + k0 + tm4];
            unsigned a2 = uA[(r0+t4)*132   + k0 + tm4 + 4];
            unsigned a3 = uA[(r0+t4+8)*132 + k0 + tm4 + 4];
            #pragma unroll
            for (int nt = 0; nt < 16; nt++) {
                int cb = c0 + nt*8 + t4;
                unsigned bb0 = uW3[(k0+tm4)*264   + cb];
                unsigned bb1 = uW3[(k0+tm4+4)*264 + cb];
                mma8(C[nt], a0, a1, a2, a3, bb0, bb1);
            }
        }
        bool oka = (r0 + t4) < cnt, okb = (r0 + t4 + 8) < cnt;
        #pragma unroll
        for (int nt = 0; nt < 16; nt++) {
            int col = c0 + nt*8 + 2*tm4;
            float m0 = oka ? (C[nt][0] + fb3[col])   : NEGB;
            float m1 = oka ? (C[nt][1] + fb3[col+1]) : NEGB;
            if (okb) {
                m0 = fmaxf(m0, C[nt][2] + fb3[col]);
                m1 = fmaxf(m1, C[nt][3] + fb3[col+1]);
            }
            #pragma unroll
            for (int off = 16; off >= 4; off >>= 1) {
                m0 = fmaxf(m0, __shfl_xor_sync(0xffffffffu, m0, off));
                m1 = fmaxf(m1, __shfl_xor_sync(0xffffffffu, m1, off));
            }
            if (t4 == 0) {
                sPart[(w&3)*256 + col]     = m0;
                sPart[(w&3)*256 + col + 1] = m1;
            }
        }
        __syncthreads();
        {
            float m = fmaxf(fmaxf(sPart[tid], sPart[256+tid]),
                            fmaxf(sPart[512+tid], sPart[768+tid]));
            g_x2cat[(size_t)q*259 + tid] = fmaxf(m, 0.f);
            if (tid < 3)
                g_x2cat[(size_t)q*259 + 256 + tid] = g_pos2[(size_t)q*3 + tid];
        }
        __syncthreads();
    }
}

// ============ tf32 GEMM (128x64 tile) with optional fused group-max ==========
template<int GMAX>
__global__ __launch_bounds__(256) void gemm_tf32(const float* __restrict__ A,
    const float* __restrict__ W, const float* __restrict__ bias,
    float* __restrict__ C, int M, int N, int K, int relu)
{
    __shared__ unsigned uA[128*20];
    __shared__ unsigned uW[16*72];
    __shared__ float sPart[4*64];
    int tid = threadIdx.x;
    int lane = tid & 31, w = tid >> 5;
    int t4 = lane >> 2, tm4 = lane & 3;
    int r0 = (w & 3) * 32, c0 = (w >> 2) * 32;
    int row0 = blockIdx.y * 128, col0 = blockIdx.x * 64;

    float acc[2][4][4];
    #pragma unroll
    for (int mt = 0; mt < 2; mt++)
        #pragma unroll
        for (int nt = 0; nt < 4; nt++)
            #pragma unroll
            for (int j = 0; j < 4; j++) acc[mt][nt][j] = 0.f;

    int nk = (K + 15) >> 4;
    for (int ks = 0; ks < nk; ks++) {
        int k0 = ks * 16;
        #pragma unroll
        for (int l = 0; l < 8; l++) {
            int idx = tid + l*256;
            int r = idx >> 4, c = idx & 15;
            int gc = k0 + c;
            uA[r*20 + c] = (gc < K) ? f2tf(A[(size_t)(row0 + r)*K + gc]) : 0u;
        }
        #pragma unroll
        for (int l = 0; l < 4; l++) {
            int idx = tid + l*256;
            int r = idx >> 6, c = idx & 63;
            int gr = k0 + r;
            uW[r*72 + c] = (gr < K) ? f2tf(W[(size_t)gr*N + col0 + c]) : 0u;
        }
        __syncthreads();
        #pragma unroll
        for (int kk = 0; kk < 16; kk += 8) {
            unsigned a0[2], a1[2], a2[2], a3[2];
            #pragma unroll
            for (int mt = 0; mt < 2; mt++) {
                a0[mt] = uA[(r0 + mt*16 + t4)*20   + kk + tm4];
                a1[mt] = uA[(r0 + mt*16 + t4+8)*20 + kk + tm4];
                a2[mt] = uA[(r0 + mt*16 + t4)*20   + kk + tm4 + 4];
                a3[mt] = uA[(r0 + mt*16 + t4+8)*20 + kk + tm4 + 4];
            }
            #pragma unroll
            for (int nt = 0; nt < 4; nt++) {
                int cb = c0 + nt*8 + t4;
                unsigned bb0 = uW[(kk+tm4)*72   + cb];
                unsigned bb1 = uW[(kk+tm4+4)*72 + cb];
                #pragma unroll
                for (int mt = 0; mt < 2; mt++)
                    mma8(acc[mt][nt], a0[mt], a1[mt], a2[mt], a3[mt], bb0, bb1);
            }
        }
        __syncthreads();
    }
    if (GMAX) {
        #pragma unroll
        for (int nt = 0; nt < 4; nt++) {
            int colr = c0 + nt*8 + 2*tm4;
            float bq0 = bias[col0 + colr], bq1 = bias[col0 + colr + 1];
            float m0 = fmaxf(fmaxf(acc[0][nt][0], acc[0][nt][2]),
                             fmaxf(acc[1][nt][0], acc[1][nt][2])) + bq0;
            float m1 = fmaxf(fmaxf(acc[0][nt][1], acc[0][nt][3]),
                             fmaxf(acc[1][nt][1], acc[1][nt][3])) + bq1;
            #pragma unroll
            for (int off = 16; off >= 4; off >>= 1) {
                m0 = fmaxf(m0, __shfl_xor_sync(0xffffffffu, m0, off));
                m1 = fmaxf(m1, __shfl_xor_sync(0xffffffffu, m1, off));
            }
            if (t4 == 0) {
                sPart[(w&3)*64 + colr]     = m0;
                sPart[(w&3)*64 + colr + 1] = m1;
            }
        }
        __syncthreads();
        if (tid < 64) {
            float m = fmaxf(fmaxf(sPart[tid], sPart[64+tid]),
                            fmaxf(sPart[128+tid], sPart[192+tid]));
            C[(size_t)blockIdx.y*1024 + col0 + tid] = m;
        }
    } else {
        #pragma unroll
        for (int mt = 0; mt < 2; mt++) {
            #pragma unroll
            for (int nt = 0; nt < 4; nt++) {
                int gc = col0 + c0 + nt*8 + 2*tm4;
                float v0 = acc[mt][nt][0] + bias[gc];
                float v1 = acc[mt][nt][1] + bias[gc+1];
                float v2 = acc[mt][nt][2] + bias[gc];
                float v3 = acc[mt][nt][3] + bias[gc+1];
                if (relu) {
                    v0 = fmaxf(v0, 0.f); v1 = fmaxf(v1, 0.f);
                    v2 = fmaxf(v2, 0.f); v3 = fmaxf(v3, 0.f);
                }
                int gr = row0 + r0 + mt*16 + t4;
                *(float2*)(C + (size_t)gr*N + gc)     = make_float2(v0, v1);
                *(float2*)(C + (size_t)(gr+8)*N + gc) = make_float2(v2, v3);
            }
        }
    }
}

// ----------------- fused head: f2 @ l3w + b, mean, quat-normalize -------------
__global__ void headfinal_kernel(const float* __restrict__ l3w, const float* __restrict__ l3b,
                                 float* __restrict__ out)
{
    __shared__ float sf3[32*7];
    __shared__ float sm[8][7];
    int t = threadIdx.x;
    if (t < 224) {
        int row = t / 7, col = t % 7;
        const float* a = g_f2 + (size_t)row*256;
        float s = 0.f;
        for (int k = 0; k < 256; k++) s = fmaf(a[k], l3w[k*7 + col], s);
        sf3[row*7 + col] = s + l3b[col];
    }
    __syncthreads();
    if (t < 56) {
        int b = t / 7, c = t % 7;
        float s = sf3[(b*4)*7+c] + sf3[(b*4+1)*7+c] + sf3[(b*4+2)*7+c] + sf3[(b*4+3)*7+c];
        sm[b][c] = s * 0.25f;
    }
    __syncthreads();
    if (t < 8) {
        float q0 = sm[t][3], q1 = sm[t][4], q2 = sm[t][5], q3 = sm[t][6];
        float nrm = sqrtf(q0*q0 + q1*q1 + q2*q2 + q3*q3);
        float d = fmaxf(nrm, 1e-12f);
        out[t*7+0] = sm[t][0]; out[t*7+1] = sm[t][1]; out[t*7+2] = sm[t][2];
        out[t*7+3] = q0/d; out[t*7+4] = q1/d; out[t*7+5] = q2/d; out[t*7+6] = q3/d;
    }
}

// ----------------- launcher --------------------------------------------------
extern "C" void kernel_launch(void* const* d_in, const int* in_sizes, int n_in,
                              void* d_out, int out_size)
{
    const float* pts  = (const float*)d_in[0];
    const float *s1w1 = (const float*)d_in[1],  *s1b1 = (const float*)d_in[2];
    const float *s1w2 = (const float*)d_in[3],  *s1b2 = (const float*)d_in[4];
    const float *s1w3 = (const float*)d_in[5],  *s1b3 = (const float*)d_in[6];
    const float *s2w1 = (const float*)d_in[7],  *s2b1 = (const float*)d_in[8];
    const float *s2w2 = (const float*)d_in[9],  *s2b2 = (const float*)d_in[10];
    const float *s2w3 = (const float*)d_in[11], *s2b3 = (const float*)d_in[12];
    const float *gw1  = (const float*)d_in[13], *gb1  = (const float*)d_in[14];
    const float *gw2  = (const float*)d_in[15], *gb2  = (const float*)d_in[16];
    const float *gw3  = (const float*)d_in[17], *gb3  = (const float*)d_in[18];
    const float *l1w  = (const float*)d_in[19], *l1b  = (const float*)d_in[20];
    const float *l2w  = (const float*)d_in[21], *l2b  = (const float*)d_in[22];
    const float *l3w  = (const float*)d_in[23], *l3b  = (const float*)d_in[24];

    float *pool, *pos1, *pos2, *x2cat, *g1b, *g2b, *gmx, *f1, *f2;
    int *nidx1, *cnt1, *nidx2, *cnt2;
    cudaGetSymbolAddress((void**)&pool,  g_pool);
    cudaGetSymbolAddress((void**)&pos1,  g_pos1);
    cudaGetSymbolAddress((void**)&pos2,  g_pos2);
    cudaGetSymbolAddress((void**)&nidx1, g_nidx1);
    cudaGetSymbolAddress((void**)&cnt1,  g_cnt1);
    cudaGetSymbolAddress((void**)&nidx2, g_nidx2);
    cudaGetSymbolAddress((void**)&cnt2,  g_cnt2);
    cudaGetSymbolAddress((void**)&x2cat, g_x2cat);
    cudaGetSymbolAddress((void**)&g1b,   g_g1);
    cudaGetSymbolAddress((void**)&g2b,   g_g2);
    cudaGetSymbolAddress((void**)&gmx,   g_gmx);
    cudaGetSymbolAddress((void**)&f1,    g_f1);
    cudaGetSymbolAddress((void**)&f2,    g_f2);
    float* h2s2 = pool;

    static cudaStream_t side1 = 0, side2 = 0;
    static cudaEvent_t evC[4], evS1 = 0, evS2 = 0;
    static int attr_done = 0;
    if (!attr_done) {
        cudaFuncSetAttribute(fps_kernel<32>, cudaFuncAttributeMaxDynamicSharedMemorySize, 4096*12 + 64);
        cudaFuncSetAttribute(fps_kernel<16>, cudaFuncAttributeMaxDynamicSharedMemorySize, 2048*12 + 64);
        cudaFuncSetAttribute(s1_fused,  cudaFuncAttributeMaxDynamicSharedMemorySize, 97280);
        cudaFuncSetAttribute(s2a_fused, cudaFuncAttributeMaxDynamicSharedMemorySize, 216320);
        cudaFuncSetAttribute(s2b_fused, cudaFuncAttributeMaxDynamicSharedMemorySize, 174080);
        cudaStreamCreateWithFlags(&side1, cudaStreamNonBlocking);
        cudaStreamCreateWithFlags(&side2, cudaStreamNonBlocking);
        for (int k = 0; k < 4; k++) cudaEventCreateWithFlags(&evC[k], cudaEventDisableTiming);
        cudaEventCreateWithFlags(&evS1, cudaEventDisableTiming);
        cudaEventCreateWithFlags(&evS2, cudaEventDisableTiming);
        attr_done = 1;
    }

    float r2a = (float)(0.1*0.1), r2b = (float)(0.2*0.2);

    // ---- fps32 in 4 chunks on main stream ----
    for (int k = 0; k < 4; k++) {
        fps_kernel<32><<<8, 128, 4096*12 + 64>>>(pts, pos1, 4096, k*512, (k+1)*512);
        cudaEventRecord(evC[k], 0);
    }

    // ---- side1: radius1 + s1 chunks trail the fps chunks ----
    for (int k = 0; k < 4; k++) {
        cudaStreamWaitEvent(side1, evC[k], 0);
        radius_kernel<<<512, 256, 0, side1>>>(pts, pos1, 4096, 2048, r2a, nidx1, cnt1, k*512, 512);
        s1_fused<<<1024, 256, 97280, side1>>>(pts, s1w1, s1b1, s1w2, s1b2, s1w3, s1b3, k*512);
    }
    cudaEventRecord(evS1, side1);

    // ---- side2: fps16 + radius2 after pos1 complete ----
    cudaStreamWaitEvent(side2, evC[3], 0);
    fps_kernel<16><<<8, 128, 2048*12 + 64, side2>>>(pos1, pos2, 2048, 0, 512);
    radius_kernel<<<512, 256, 0, side2>>>(pos1, pos2, 2048, 512, r2b, nidx2, cnt2, 0, 512);
    cudaEventRecord(evS2, side2);

    // ---- main: join, then stage-2 + global MLP + head ----
    cudaStreamWaitEvent(0, evS1, 0);
    cudaStreamWaitEvent(0, evS2, 0);
    s2a_fused<<<1024, 256, 216320>>>(s2w1, s2b1, s2w2, s2b2, h2s2);
    s2b_fused<<<1024, 256, 174080>>>(h2s2, s2w3, s2b3);

    gemm_tf32<0><<<dim3(4, 32), 256>>>(x2cat, gw1, gb1, g1b, 4096, 256, 259, 1);
    gemm_tf32<0><<<dim3(8, 32), 256>>>(g1b, gw2, gb2, g2b, 4096, 512, 256, 1);
    gemm_tf32<1><<<dim3(16, 32), 256>>>(g2b, gw3, gb3, gmx, 4096, 1024, 512, 0);
    gemm_tf32<0><<<dim3(8, 1), 256>>>(gmx, l1w, l1b, f1, 128, 512, 1024, 1);
    gemm_tf32<0><<<dim3(4, 1), 256>>>(f1, l2w, l2b, f2, 128, 256, 512, 1);
    headfinal_kernel<<<1, 256>>>(l3w, l3b, (float*)d_out);
}

// round 17
// speedup vs baseline: 1.2407x; 1.0220x over previous
#include <cuda_runtime.h>
#include <math.h>

#define NEGB -1.0e30f

// ----------------- scratch -----------------
__device__ float g_pool[67108864];
__device__ float g_pos1[8*2048*3];
__device__ float g_pos2[8*512*3];
__device__ int   g_nidx1[8*2048*64];
__device__ int   g_cnt1[8*2048];
__device__ int   g_nidx2[8*512*64];
__device__ int   g_cnt2[8*512];
__device__ float g_x1[8*2048*128];
__device__ float g_x2cat[8*512*259];
__device__ float g_g1[8*512*256];
__device__ float g_g2[8*512*512];
__device__ float g_gmx[128*1024];
__device__ float g_f1[128*512];
__device__ float g_f2[128*256];
__device__ float g_mind[8*4096];
__device__ int   g_bidx[8];

// ---- packed f32x2 helpers ----
__device__ __forceinline__ unsigned long long pk2(float lo, float hi) {
    unsigned long long r; asm("mov.b64 %0, {%1, %2};" : "=l"(r) : "f"(lo), "f"(hi)); return r;
}
__device__ __forceinline__ void upk2(unsigned long long v, float& lo, float& hi) {
    asm("mov.b64 {%0, %1}, %2;" : "=f"(lo), "=f"(hi) : "l"(v));
}
__device__ __forceinline__ unsigned long long add2(unsigned long long a, unsigned long long b) {
    unsigned long long r; asm("add.rn.f32x2 %0, %1, %2;" : "=l"(r) : "l"(a), "l"(b)); return r;
}
__device__ __forceinline__ unsigned long long mul2(unsigned long long a, unsigned long long b) {
    unsigned long long r; asm("mul.rn.f32x2 %0, %1, %2;" : "=l"(r) : "l"(a), "l"(b)); return r;
}

// ---- tf32 mma helpers ----
__device__ __forceinline__ unsigned f2tf(float f) {
    unsigned r; asm("cvt.rna.tf32.f32 %0, %1;" : "=r"(r) : "f"(f)); return r;
}
__device__ __forceinline__ void mma8(float c[4], unsigned a0, unsigned a1, unsigned a2, unsigned a3,
                                     unsigned b0, unsigned b1) {
    asm volatile("mma.sync.aligned.m16n8k8.row.col.f32.tf32.tf32.f32 "
                 "{%0,%1,%2,%3},{%4,%5,%6,%7},{%8,%9},{%0,%1,%2,%3};"
                 : "+f"(c[0]), "+f"(c[1]), "+f"(c[2]), "+f"(c[3])
                 : "r"(a0), "r"(a1), "r"(a2), "r"(a3), "r"(b0), "r"(b1));
}

// ----------------- FPS chunked (state carried in g_mind/g_bidx) --------------
template<int PT>
__global__ __launch_bounds__(128) void fps_kernel(const float* __restrict__ posIn,
                                                  float* __restrict__ posOut,
                                                  int N, int s0, int s1e)
{
    extern __shared__ float sm[];
    float* spx = sm;
    float* spy = sm + N;
    float* spz = sm + 2*N;
    unsigned long long* part = (unsigned long long*)(sm + 3*N);

    int b = blockIdx.x, t = threadIdx.x;
    int lane = t & 31, warp = t >> 5;
    const float* p = posIn + (size_t)b*N*3;
    unsigned long long pxp[PT/2], pyp[PT/2], pzp[PT/2];
    float mind[PT];
    #pragma unroll
    for (int jj = 0; jj < PT/2; jj++) {
        int i0 = (2*jj)*128 + t, i1 = (2*jj+1)*128 + t;
        float x0 = p[3*i0], y0 = p[3*i0+1], z0 = p[3*i0+2];
        float x1 = p[3*i1], y1 = p[3*i1+1], z1 = p[3*i1+2];
        spx[i0] = x0; spy[i0] = y0; spz[i0] = z0;
        spx[i1] = x1; spy[i1] = y1; spz[i1] = z1;
        pxp[jj] = pk2(x0, x1); pyp[jj] = pk2(y0, y1); pzp[jj] = pk2(z0, z1);
    }
    int S = (N == 4096) ? 2048 : 512;
    if (s0 == 0) {
        #pragma unroll
        for (int j = 0; j < PT; j++) mind[j] = 3.402823466e38f;
        if (t == 0) {
            float* o = posOut + (size_t)b*S*3;
            o[0] = p[0]; o[1] = p[1]; o[2] = p[2];
        }
    } else {
        #pragma unroll
        for (int j = 0; j < PT; j++) mind[j] = g_mind[(size_t)b*N + j*128 + t];
    }
    __syncthreads();
    int bidx = (s0 == 0) ? 0 : g_bidx[b];
    for (int s = (s0 == 0 ? 1 : s0); s < s1e; s++) {
        float lx = spx[bidx], ly = spy[bidx], lz = spz[bidx];
        unsigned long long nx = pk2(-lx, -lx), ny = pk2(-ly, -ly), nz = pk2(-lz, -lz);
        float bva[4] = {NEGB, NEGB, NEGB, NEGB};
        #pragma unroll
        for (int jj = 0; jj < PT/2; jj++) {
            unsigned long long dx = add2(pxp[jj], nx);
            unsigned long long dy = add2(pyp[jj], ny);
            unsigned long long dz = add2(pzp[jj], nz);
            unsigned long long d2 = add2(add2(mul2(dx,dx), mul2(dy,dy)), mul2(dz,dz));
            float dlo, dhi; upk2(d2, dlo, dhi);
            float m0 = fminf(mind[2*jj],   dlo); mind[2*jj]   = m0;
            float m1 = fminf(mind[2*jj+1], dhi); mind[2*jj+1] = m1;
            bva[jj & 3] = fmaxf(bva[jj & 3], fmaxf(m0, m1));
        }
        float bv = fmaxf(fmaxf(bva[0], bva[1]), fmaxf(bva[2], bva[3]));
        unsigned vb = __float_as_uint(bv);
        unsigned vmax = __reduce_max_sync(0xffffffffu, vb);
        int cand = 0x7fffffff;
        if (vb == vmax) {
            #pragma unroll
            for (int j = PT-1; j >= 0; j--)
                if (__float_as_uint(mind[j]) == vmax) cand = j*128 + t;
        }
        int widx = __reduce_min_sync(0xffffffffu, cand);
        if (lane == 0)
            part[(s & 1)*4 + warp] =
                ((unsigned long long)vmax << 32) | (unsigned)(0xFFFFFFFFu - (unsigned)widx);
        __syncthreads();
        const unsigned long long* pp = part + (s & 1)*4;
        unsigned long long k0 = pp[0], k1 = pp[1], k2 = pp[2], k3 = pp[3];
        k0 = k0 > k1 ? k0 : k1;
        k2 = k2 > k3 ? k2 : k3;
        k0 = k0 > k2 ? k0 : k2;
        bidx = (int)(0xFFFFFFFFu - (unsigned)(k0 & 0xFFFFFFFFu));
        if (t == 0) {
            float* o = posOut + ((size_t)b*S + s)*3;
            o[0] = spx[bidx]; o[1] = spy[bidx]; o[2] = spz[bidx];
        }
    }
    if (s1e < S) {
        #pragma unroll
        for (int j = 0; j < PT; j++) g_mind[(size_t)b*N + j*128 + t] = mind[j];
        if (t == 0) g_bidx[b] = bidx;
    }
}

// ----------------- radius NN (chunked) ---------------------------------------
__global__ void radius_kernel(const float* __restrict__ posAll, const float* __restrict__ posQ,
                              int N, int M, float r2,
                              int* __restrict__ nidx, int* __restrict__ cnt,
                              int sOff, int chunkS)
{
    __shared__ unsigned long long cand[8][256];
    __shared__ int scnt[8];
    int warp = threadIdx.x >> 5, lane = threadIdx.x & 31;
    int qLocal = blockIdx.x * 8 + warp;
    int b = qLocal / chunkS;
    int q = b*M + sOff + (qLocal - b*chunkS);
    if (lane == 0) scnt[warp] = 0;
    __syncwarp();
    const float* qp = posQ + (size_t)q*3;
    float qx = qp[0], qy = qp[1], qz = qp[2];
    const float* p = posAll + (size_t)b*N*3;
    for (int i = lane; i < N; i += 32) {
        float dx = __fsub_rn(qx, p[3*i]);
        float dy = __fsub_rn(qy, p[3*i+1]);
        float dz = __fsub_rn(qz, p[3*i+2]);
        float d2 = __fadd_rn(__fadd_rn(__fmul_rn(dx,dx), __fmul_rn(dy,dy)), __fmul_rn(dz,dz));
        if (d2 <= r2) {
            int pos = atomicAdd(&scnt[warp], 1);
            if (pos < 256)
                cand[warp][pos] = ((unsigned long long)__float_as_uint(d2) << 32) | (unsigned)i;
        }
    }
    __syncwarp();
    int c = scnt[warp]; if (c > 256) c = 256;
    int* out = nidx + (size_t)q*64;
    if (c <= 64) {
        for (int t = lane; t < c; t += 32) out[t] = (int)(cand[warp][t] & 0xffffffffu);
        if (lane == 0) cnt[q] = c;
    } else {
        int slots = (c + 31) >> 5;
        for (int sel = 0; sel < 64; sel++) {
            unsigned long long best = ~0ULL;
            for (int k = 0; k < slots; k++) {
                int j = lane + (k << 5);
                if (j < c) { unsigned long long v = cand[warp][j]; if (v < best) best = v; }
            }
            #pragma unroll
            for (int off = 16; off; off >>= 1) {
                unsigned long long o = __shfl_down_sync(0xffffffffu, best, off);
                if (o < best) best = o;
            }
            best = __shfl_sync(0xffffffffu, best, 0);
            if (lane == 0) out[sel] = (int)(best & 0xffffffffu);
            for (int k = 0; k < slots; k++) {
                int j = lane + (k << 5);
                if (j < c && cand[warp][j] == best) cand[warp][j] = ~0ULL;
            }
        }
        if (lane == 0) cnt[q] = 64;
    }
}

// ============ Stage-1: scalar layer1 + tf32 mma layers 2/3, QPB=4, chunked ===
__global__ __launch_bounds__(256) void s1_fused(const float* __restrict__ pts,
    const float* __restrict__ w1, const float* __restrict__ b1,
    const float* __restrict__ w2, const float* __restrict__ b2,
    const float* __restrict__ w3, const float* __restrict__ b3, int sOff)
{
    extern __shared__ unsigned usm[];
    unsigned* uW2 = usm;
    unsigned* uW3 = usm + 4608;
    unsigned* uH1 = usm + 13312;
    unsigned* uH2 = usm + 18176;
    float* fW1  = (float*)(usm + 23040);
    float* fB1  = (float*)(usm + 23232);
    float* fB2  = (float*)(usm + 23296);
    float* fB3  = (float*)(usm + 23360);
    float* fRel = (float*)(usm + 23488);
    float* fPart= (float*)(usm + 23744);

    int tid = threadIdx.x;
    int lane = tid & 31, w = tid >> 5;
    int t4 = lane >> 2, tm4 = lane & 3;
    int r0 = (w & 3) * 16;

    for (int i = tid; i < 192;  i += 256) fW1[i] = w1[i];
    for (int i = tid; i < 64;   i += 256) { fB1[i] = b1[i]; fB2[i] = b2[i]; }
    if (tid < 128) fB3[tid] = b3[tid];
    for (int i = tid; i < 4608; i += 256) {
        int k = i / 72, n = i - k*72;
        uW2[i] = (n < 64) ? f2tf(w2[k*64 + n]) : 0u;
    }
    for (int i = tid; i < 8704; i += 256) {
        int k = i / 136, n = i - k*136;
        uW3[i] = (n < 128) ? f2tf(w3[k*128 + n]) : 0u;
    }

    for (int qi = 0; qi < 4; qi++) {
        int qLocal = blockIdx.x*4 + qi;
        int b = qLocal >> 9;
        int q = b*2048 + sOff + (qLocal & 511);
        int cnt = g_cnt1[q];
        if (tid < 64) {
            int idx = (tid < cnt) ? g_nidx1[q*64 + tid] : 0;
            const float* sp = pts + ((size_t)b*4096 + idx)*3;
            const float* qp = g_pos1 + (size_t)q*3;
            fRel[tid*4+0] = sp[0] - qp[0];
            fRel[tid*4+1] = sp[1] - qp[1];
            fRel[tid*4+2] = sp[2] - qp[2];
        }
        __syncthreads();
        {
            int m = tid >> 2, j0 = (tid & 3) * 16;
            float rx = fRel[m*4], ry = fRel[m*4+1], rz = fRel[m*4+2];
            #pragma unroll
            for (int j = 0; j < 16; j++) {
                int c = j0 + j;
                float v = fmaf(rz, fW1[128+c], fmaf(ry, fW1[64+c], fmaf(rx, fW1[c], fB1[c])));
                uH1[m*76 + c] = f2tf(fmaxf(v, 0.f));
            }
        }
        __syncthreads();
        int active = (r0 < cnt);
        if (active) {
            int c0 = (w >> 2) * 32;
            float acc[4][4];
            #pragma unroll
            for (int nt = 0; nt < 4; nt++) { acc[nt][0]=acc[nt][1]=acc[nt][2]=acc[nt][3]=0.f; }
            #pragma unroll
            for (int kk = 0; kk < 64; kk += 8) {
                unsigned a0 = uH1[(r0+t4)*76   + kk + tm4];
                unsigned a1 = uH1[(r0+t4+8)*76 + kk + tm4];
                unsigned a2 = uH1[(r0+t4)*76   + kk + tm4 + 4];
                unsigned a3 = uH1[(r0+t4+8)*76 + kk + tm4 + 4];
                #pragma unroll
                for (int nt = 0; nt < 4; nt++) {
                    int cb = c0 + nt*8 + t4;
                    unsigned bb0 = uW2[(kk+tm4)*72   + cb];
                    unsigned bb1 = uW2[(kk+tm4+4)*72 + cb];
                    mma8(acc[nt], a0, a1, a2, a3, bb0, bb1);
                }
            }
            #pragma unroll
            for (int nt = 0; nt < 4; nt++) {
                int col = c0 + nt*8 + 2*tm4;
                uH2[(r0+t4)*76   + col]   = f2tf(fmaxf(acc[nt][0] + fB2[col],   0.f));
                uH2[(r0+t4)*76   + col+1] = f2tf(fmaxf(acc[nt][1] + fB2[col+1], 0.f));
                uH2[(r0+t4+8)*76 + col]   = f2tf(fmaxf(acc[nt][2] + fB2[col],   0.f));
                uH2[(r0+t4+8)*76 + col+1] = f2tf(fmaxf(acc[nt][3] + fB2[col+1], 0.f));
            }
        }
        __syncthreads();
        if (active) {
            int c0 = (w >> 2) * 64;
            float acc[8][4];
            #pragma unroll
            for (int nt = 0; nt < 8; nt++) { acc[nt][0]=acc[nt][1]=acc[nt][2]=acc[nt][3]=0.f; }
            #pragma unroll
            for (int kk = 0; kk < 64; kk += 8) {
                unsigned a0 = uH2[(r0+t4)*76   + kk + tm4];
                unsigned a1 = uH2[(r0+t4+8)*76 + kk + tm4];
                unsigned a2 = uH2[(r0+t4)*76   + kk + tm4 + 4];
                unsigned a3 = uH2[(r0+t4+8)*76 + kk + tm4 + 4];
                #pragma unroll
                for (int nt = 0; nt < 8; nt++) {
                    int cb = c0 + nt*8 + t4;
                    unsigned bb0 = uW3[(kk+tm4)*136   + cb];
                    unsigned bb1 = uW3[(kk+tm4+4)*136 + cb];
                    mma8(acc[nt], a0, a1, a2, a3, bb0, bb1);
                }
            }
            bool oka = (r0 + t4) < cnt, okb = (r0 + t4 + 8) < cnt;
            #pragma unroll
            for (int nt = 0; nt < 8; nt++) {
                int col = c0 + nt*8 + 2*tm4;
                float m0 = oka ? (acc[nt][0] + fB3[col])   : NEGB;
                float m1 = oka ? (acc[nt][1] + fB3[col+1]) : NEGB;
                if (okb) {
                    m0 = fmaxf(m0, acc[nt][2] + fB3[col]);
                    m1 = fmaxf(m1, acc[nt][3] + fB3[col+1]);
                }
                #pragma unroll
                for (int off = 16; off >= 4; off >>= 1) {
                    m0 = fmaxf(m0, __shfl_xor_sync(0xffffffffu, m0, off));
                    m1 = fmaxf(m1, __shfl_xor_sync(0xffffffffu, m1, off));
                }
                if (t4 == 0) {
                    fPart[(w&3)*128 + col]     = m0;
                    fPart[(w&3)*128 + col + 1] = m1;
                }
            }
        }
        __syncthreads();
        if (tid < 128) {
            int nrt = (cnt + 15) >> 4; if (nrt > 4) nrt = 4;
            float m = NEGB;
            for (int r = 0; r < nrt; r++) m = fmaxf(m, fPart[r*128 + tid]);
            g_x1[(size_t)q*128 + tid] = fmaxf(m, 0.f);
        }
        __syncthreads();
    }
}

// ============ Stage-2 part A: tf32 mma (131->128->128), QPB=4, chunked =======
__global__ __launch_bounds__(256) void s2a_fused(
    const float* __restrict__ w1, const float* __restrict__ b1,
    const float* __restrict__ w2, const float* __restrict__ b2,
    float* __restrict__ h2out, int sOff)
{
    extern __shared__ unsigned usm[];
    unsigned* uW1 = usm;
    unsigned* uW2 = usm + 18496;
    unsigned* uA  = usm + 35904;
    unsigned* uH1 = usm + 44864;
    float* fb1 = (float*)(usm + 53824);
    float* fb2 = (float*)(usm + 53952);

    int tid = threadIdx.x;
    int lane = tid & 31, w = tid >> 5;
    int t4 = lane >> 2, tm4 = lane & 3;
    int r0 = (w & 3) * 16, c0 = (w >> 2) * 64;

    for (int i = tid; i < 18496; i += 256) {
        int k = i / 136, n = i - k*136;
        uW1[i] = (k < 131 && n < 128) ? f2tf(w1[k*128 + n]) : 0u;
    }
    for (int i = tid; i < 17408; i += 256) {
        int k = i / 136, n = i - k*136;
        uW2[i] = (n < 128) ? f2tf(w2[k*128 + n]) : 0u;
    }
    if (tid < 128) { fb1[tid] = b1[tid]; fb2[tid] = b2[tid]; }

    for (int qi = 0; qi < 4; qi++) {
        int qLocal = blockIdx.x*4 + qi;          // 0..2047 per chunk
        int b = qLocal >> 8;
        int q = b*512 + sOff + (qLocal & 255);
        int cnt = g_cnt2[q];
        {
            int m = tid >> 2, l4 = tid & 3;
            int idx = (m < cnt) ? g_nidx2[q*64 + m] : 0;
            const float4* src = (const float4*)(g_x1 + ((size_t)b*2048 + idx)*128);
            #pragma unroll
            for (int j = 0; j < 8; j++) {
                float4 v = src[l4*8 + j];
                unsigned* d = uA + m*140 + l4*32 + j*4;
                d[0] = f2tf(v.x); d[1] = f2tf(v.y); d[2] = f2tf(v.z); d[3] = f2tf(v.w);
            }
            if (l4 == 0) {
                const float* ps = g_pos1 + ((size_t)b*2048 + idx)*3;
                const float* pq = g_pos2 + (size_t)q*3;
                uA[m*140+128] = f2tf(ps[0]-pq[0]);
                uA[m*140+129] = f2tf(ps[1]-pq[1]);
                uA[m*140+130] = f2tf(ps[2]-pq[2]);
                #pragma unroll
                for (int z = 131; z < 140; z++) uA[m*140+z] = 0u;
            }
        }
        __syncthreads();
        {
            float C1[8][4];
            #pragma unroll
            for (int nt = 0; nt < 8; nt++) { C1[nt][0]=C1[nt][1]=C1[nt][2]=C1[nt][3]=0.f; }
            for (int ks = 0; ks < 17; ks++) {
                int k0 = ks*8;
                unsigned a0 = uA[(r0+t4)*140   + k0 + tm4];
                unsigned a1 = uA[(r0+t4+8)*140 + k0 + tm4];
                unsigned a2 = uA[(r0+t4)*140   + k0 + tm4 + 4];
                unsigned a3 = uA[(r0+t4+8)*140 + k0 + tm4 + 4];
                #pragma unroll
                for (int nt = 0; nt < 8; nt++) {
                    int cb = c0 + nt*8 + t4;
                    unsigned bb0 = uW1[(k0+tm4)*136   + cb];
                    unsigned bb1 = uW1[(k0+tm4+4)*136 + cb];
                    mma8(C1[nt], a0, a1, a2, a3, bb0, bb1);
                }
            }
            #pragma unroll
            for (int nt = 0; nt < 8; nt++) {
                int col = c0 + nt*8 + 2*tm4;
                uH1[(r0+t4)*140   + col]   = f2tf(fmaxf(C1[nt][0] + fb1[col],   0.f));
                uH1[(r0+t4)*140   + col+1] = f2tf(fmaxf(C1[nt][1] + fb1[col+1], 0.f));
                uH1[(r0+t4+8)*140 + col]   = f2tf(fmaxf(C1[nt][2] + fb1[col],   0.f));
                uH1[(r0+t4+8)*140 + col+1] = f2tf(fmaxf(C1[nt][3] + fb1[col+1], 0.f));
            }
        }
        __syncthreads();
        {
            float C2[8][4];
            #pragma unroll
            for (int nt = 0; nt < 8; nt++) { C2[nt][0]=C2[nt][1]=C2[nt][2]=C2[nt][3]=0.f; }
            for (int ks = 0; ks < 16; ks++) {
                int k0 = ks*8;
                unsigned a0 = uH1[(r0+t4)*140   + k0 + tm4];
                unsigned a1 = uH1[(r0+t4+8)*140 + k0 + tm4];
                unsigned a2 = uH1[(r0+t4)*140   + k0 + tm4 + 4];
                unsigned a3 = uH1[(r0+t4+8)*140 + k0 + tm4 + 4];
                #pragma unroll
                for (int nt = 0; nt < 8; nt++) {
                    int cb = c0 + nt*8 + t4;
                    unsigned bb0 = uW2[(k0+tm4)*136   + cb];
                    unsigned bb1 = uW2[(k0+tm4+4)*136 + cb];
                    mma8(C2[nt], a0, a1, a2, a3, bb0, bb1);
                }
            }
            #pragma unroll
            for (int nt = 0; nt < 8; nt++) {
                int col = c0 + nt*8 + 2*tm4;
                float2 va = make_float2(fmaxf(C2[nt][0] + fb2[col],   0.f),
                                        fmaxf(C2[nt][1] + fb2[col+1], 0.f));
                float2 vb = make_float2(fmaxf(C2[nt][2] + fb2[col],   0.f),
                                        fmaxf(C2[nt][3] + fb2[col+1], 0.f));
                *(float2*)(h2out + ((size_t)q*64 + r0+t4)*128   + col) = va;
                *(float2*)(h2out + ((size_t)q*64 + r0+t4+8)*128 + col) = vb;
            }
        }
        __syncthreads();
    }
}

// ============ Stage-2 part B: tf32 mma + masked max, QPB=4, chunked ==========
__global__ __launch_bounds__(256) void s2b_fused(
    const float* __restrict__ h2, const float* __restrict__ w3, const float* __restrict__ b3,
    int sOff)
{
    extern __shared__ unsigned usm[];
    unsigned* uW3 = usm;
    unsigned* uA  = usm + 33792;
    float* fb3   = (float*)(usm + 42240);
    float* sPart = (float*)(usm + 42496);

    int tid = threadIdx.x;
    int lane = tid & 31, w = tid >> 5;
    int t4 = lane >> 2, tm4 = lane & 3;
    int r0 = (w & 3) * 16, c0 = (w >> 2) * 128;

    for (int i = tid; i < 33792; i += 256) {
        int k = i / 264, n = i - k*264;
        uW3[i] = (n < 256) ? f2tf(w3[k*256 + n]) : 0u;
    }
    if (tid < 256) fb3[tid] = b3[tid];

    for (int qi = 0; qi < 4; qi++) {
        int qLocal = blockIdx.x*4 + qi;          // 0..2047 per chunk
        int b = qLocal >> 8;
        int q = b*512 + sOff + (qLocal & 255);
        {
            int m = tid >> 2, l4 = tid & 3;
            const float4* src = (const float4*)(h2 + ((size_t)q*64 + m)*128);
            #pragma unroll
            for (int j = 0; j < 8; j++) {
                float4 v = src[l4*8 + j];
                unsigned* d = uA + m*132 + l4*32 + j*4;
                d[0] = f2tf(v.x); d[1] = f2tf(v.y); d[2] = f2tf(v.z); d[3] = f2tf(v.w);
            }
        }
        __syncthreads();
        int cnt = g_cnt2[q];
        float C[16][4];
        #pragma unroll
        for (int nt = 0; nt < 16; nt++) { C[nt][0]=C[nt][1]=C[nt][2]=C[nt][3]=0.f; }
        for (int ks = 0; ks < 16; ks++) {
            int k0 = ks*8;
            unsigned a0 = uA[(r0+t4)*132   + k0 + tm4];
            unsigned a1 = uA[(r0+t4+8)*132 + k0 + tm4];
            unsigned a2 = uA[(r0+t4)*132   + k0 + tm4 + 4];
            unsigned a3 = uA[(r0+t4+8)*132 + k0 + tm4 + 4];
            #pragma unroll
            for (int nt = 0; nt < 16; nt++) {
                int cb = c0 + nt*8 + t4;
                unsigned bb0 = uW3[(k0+tm4)*264   + cb];
                unsigned bb1 = uW3[(k0+tm4+4)*264 + cb];
                mma8(C[nt], a0, a1, a2, a3, bb0, bb1);
            }
        }
        bool oka = (r0 + t4) < cnt, okb = (r0 + t4 + 8) < cnt;
        #pragma unroll
        for (int nt = 0; nt < 16; nt++) {
            int col = c0 + nt*8 + 2*tm4;
            float m0 = oka ? (C[nt][0] + fb3[col])   : NEGB;
            float m1 = oka ? (C[nt][1] + fb3[col+1]) : NEGB;
            if (okb) {
                m0 = fmaxf(m0, C[nt][2] + fb3[col]);
                m1 = fmaxf(m1, C[nt][3] + fb3[col+1]);
            }
            #pragma unroll
            for (int off = 16; off >= 4; off >>= 1) {
                m0 = fmaxf(m0, __shfl_xor_sync(0xffffffffu, m0, off));
                m1 = fmaxf(m1, __shfl_xor_sync(0xffffffffu, m1, off));
            }
            if (t4 == 0) {
                sPart[(w&3)*256 + col]     = m0;
                sPart[(w&3)*256 + col + 1] = m1;
            }
        }
        __syncthreads();
        {
            float m = fmaxf(fmaxf(sPart[tid], sPart[256+tid]),
                            fmaxf(sPart[512+tid], sPart[768+tid]));
            g_x2cat[(size_t)q*259 + tid] = fmaxf(m, 0.f);
            if (tid < 3)
                g_x2cat[(size_t)q*259 + 256 + tid] = g_pos2[(size_t)q*3 + tid];
        }
        __syncthreads();
    }
}

// ============ tf32 GEMM (128x64 tile) with optional fused group-max ==========
template<int GMAX>
__global__ __launch_bounds__(256) void gemm_tf32(const float* __restrict__ A,
    const float* __restrict__ W, const float* __restrict__ bias,
    float* __restrict__ C, int M, int N, int K, int relu)
{
    __shared__ unsigned uA[128*20];
    __shared__ unsigned uW[16*72];
    __shared__ float sPart[4*64];
    int tid = threadIdx.x;
    int lane = tid & 31, w = tid >> 5;
    int t4 = lane >> 2, tm4 = lane & 3;
    int r0 = (w & 3) * 32, c0 = (w >> 2) * 32;
    int row0 = blockIdx.y * 128, col0 = blockIdx.x * 64;

    float acc[2][4][4];
    #pragma unroll
    for (int mt = 0; mt < 2; mt++)
        #pragma unroll
        for (int nt = 0; nt < 4; nt++)
            #pragma unroll
            for (int j = 0; j < 4; j++) acc[mt][nt][j] = 0.f;

    int nk = (K + 15) >> 4;
    for (int ks = 0; ks < nk; ks++) {
        int k0 = ks * 16;
        #pragma unroll
        for (int l = 0; l < 8; l++) {
            int idx = tid + l*256;
            int r = idx >> 4, c = idx & 15;
            int gc = k0 + c;
            uA[r*20 + c] = (gc < K) ? f2tf(A[(size_t)(row0 + r)*K + gc]) : 0u;
        }
        #pragma unroll
        for (int l = 0; l < 4; l++) {
            int idx = tid + l*256;
            int r = idx >> 6, c = idx & 63;
            int gr = k0 + r;
            uW[r*72 + c] = (gr < K) ? f2tf(W[(size_t)gr*N + col0 + c]) : 0u;
        }
        __syncthreads();
        #pragma unroll
        for (int kk = 0; kk < 16; kk += 8) {
            unsigned a0[2], a1[2], a2[2], a3[2];
            #pragma unroll
            for (int mt = 0; mt < 2; mt++) {
                a0[mt] = uA[(r0 + mt*16 + t4)*20   + kk + tm4];
                a1[mt] = uA[(r0 + mt*16 + t4+8)*20 + kk + tm4];
                a2[mt] = uA[(r0 + mt*16 + t4)*20   + kk + tm4 + 4];
                a3[mt] = uA[(r0 + mt*16 + t4+8)*20 + kk + tm4 + 4];
            }
            #pragma unroll
            for (int nt = 0; nt < 4; nt++) {
                int cb = c0 + nt*8 + t4;
                unsigned bb0 = uW[(kk+tm4)*72   + cb];
                unsigned bb1 = uW[(kk+tm4+4)*72 + cb];
                #pragma unroll
                for (int mt = 0; mt < 2; mt++)
                    mma8(acc[mt][nt], a0[mt], a1[mt], a2[mt], a3[mt], bb0, bb1);
            }
        }
        __syncthreads();
    }
    if (GMAX) {
        #pragma unroll
        for (int nt = 0; nt < 4; nt++) {
            int colr = c0 + nt*8 + 2*tm4;
            float bq0 = bias[col0 + colr], bq1 = bias[col0 + colr + 1];
            float m0 = fmaxf(fmaxf(acc[0][nt][0], acc[0][nt][2]),
                             fmaxf(acc[1][nt][0], acc[1][nt][2])) + bq0;
            float m1 = fmaxf(fmaxf(acc[0][nt][1], acc[0][nt][3]),
                             fmaxf(acc[1][nt][1], acc[1][nt][3])) + bq1;
            #pragma unroll
            for (int off = 16; off >= 4; off >>= 1) {
                m0 = fmaxf(m0, __shfl_xor_sync(0xffffffffu, m0, off));
                m1 = fmaxf(m1, __shfl_xor_sync(0xffffffffu, m1, off));
            }
            if (t4 == 0) {
                sPart[(w&3)*64 + colr]     = m0;
                sPart[(w&3)*64 + colr + 1] = m1;
            }
        }
        __syncthreads();
        if (tid < 64) {
            float m = fmaxf(fmaxf(sPart[tid], sPart[64+tid]),
                            fmaxf(sPart[128+tid], sPart[192+tid]));
            C[(size_t)blockIdx.y*1024 + col0 + tid] = m;
        }
    } else {
        #pragma unroll
        for (int mt = 0; mt < 2; mt++) {
            #pragma unroll
            for (int nt = 0; nt < 4; nt++) {
                int gc = col0 + c0 + nt*8 + 2*tm4;
                float v0 = acc[mt][nt][0] + bias[gc];
                float v1 = acc[mt][nt][1] + bias[gc+1];
                float v2 = acc[mt][nt][2] + bias[gc];
                float v3 = acc[mt][nt][3] + bias[gc+1];
                if (relu) {
                    v0 = fmaxf(v0, 0.f); v1 = fmaxf(v1, 0.f);
                    v2 = fmaxf(v2, 0.f); v3 = fmaxf(v3, 0.f);
                }
                int gr = row0 + r0 + mt*16 + t4;
                *(float2*)(C + (size_t)gr*N + gc)     = make_float2(v0, v1);
                *(float2*)(C + (size_t)(gr+8)*N + gc) = make_float2(v2, v3);
            }
        }
    }
}

// ----------------- fused head -------------------------------------------------
__global__ void headfinal_kernel(const float* __restrict__ l3w, const float* __restrict__ l3b,
                                 float* __restrict__ out)
{
    __shared__ float sf3[32*7];
    __shared__ float sm[8][7];
    int t = threadIdx.x;
    if (t < 224) {
        int row = t / 7, col = t % 7;
        const float* a = g_f2 + (size_t)row*256;
        float s = 0.f;
        for (int k = 0; k < 256; k++) s = fmaf(a[k], l3w[k*7 + col], s);
        sf3[row*7 + col] = s + l3b[col];
    }
    __syncthreads();
    if (t < 56) {
        int b = t / 7, c = t % 7;
        float s = sf3[(b*4)*7+c] + sf3[(b*4+1)*7+c] + sf3[(b*4+2)*7+c] + sf3[(b*4+3)*7+c];
        sm[b][c] = s * 0.25f;
    }
    __syncthreads();
    if (t < 8) {
        float q0 = sm[t][3], q1 = sm[t][4], q2 = sm[t][5], q3 = sm[t][6];
        float nrm = sqrtf(q0*q0 + q1*q1 + q2*q2 + q3*q3);
        float d = fmaxf(nrm, 1e-12f);
        out[t*7+0] = sm[t][0]; out[t*7+1] = sm[t][1]; out[t*7+2] = sm[t][2];
        out[t*7+3] = q0/d; out[t*7+4] = q1/d; out[t*7+5] = q2/d; out[t*7+6] = q3/d;
    }
}

// ----------------- launcher --------------------------------------------------
extern "C" void kernel_launch(void* const* d_in, const int* in_sizes, int n_in,
                              void* d_out, int out_size)
{
    const float* pts  = (const float*)d_in[0];
    const float *s1w1 = (const float*)d_in[1],  *s1b1 = (const float*)d_in[2];
    const float *s1w2 = (const float*)d_in[3],  *s1b2 = (const float*)d_in[4];
    const float *s1w3 = (const float*)d_in[5],  *s1b3 = (const float*)d_in[6];
    const float *s2w1 = (const float*)d_in[7],  *s2b1 = (const float*)d_in[8];
    const float *s2w2 = (const float*)d_in[9],  *s2b2 = (const float*)d_in[10];
    const float *s2w3 = (const float*)d_in[11], *s2b3 = (const float*)d_in[12];
    const float *gw1  = (const float*)d_in[13], *gb1  = (const float*)d_in[14];
    const float *gw2  = (const float*)d_in[15], *gb2  = (const float*)d_in[16];
    const float *gw3  = (const float*)d_in[17], *gb3  = (const float*)d_in[18];
    const float *l1w  = (const float*)d_in[19], *l1b  = (const float*)d_in[20];
    const float *l2w  = (const float*)d_in[21], *l2b  = (const float*)d_in[22];
    const float *l3w  = (const float*)d_in[23], *l3b  = (const float*)d_in[24];

    float *pool, *pos1, *pos2, *x2cat, *g1b, *g2b, *gmx, *f1, *f2;
    int *nidx1, *cnt1, *nidx2, *cnt2;
    cudaGetSymbolAddress((void**)&pool,  g_pool);
    cudaGetSymbolAddress((void**)&pos1,  g_pos1);
    cudaGetSymbolAddress((void**)&pos2,  g_pos2);
    cudaGetSymbolAddress((void**)&nidx1, g_nidx1);
    cudaGetSymbolAddress((void**)&cnt1,  g_cnt1);
    cudaGetSymbolAddress((void**)&nidx2, g_nidx2);
    cudaGetSymbolAddress((void**)&cnt2,  g_cnt2);
    cudaGetSymbolAddress((void**)&x2cat, g_x2cat);
    cudaGetSymbolAddress((void**)&g1b,   g_g1);
    cudaGetSymbolAddress((void**)&g2b,   g_g2);
    cudaGetSymbolAddress((void**)&gmx,   g_gmx);
    cudaGetSymbolAddress((void**)&f1,    g_f1);
    cudaGetSymbolAddress((void**)&f2,    g_f2);
    float* h2s2 = pool;

    static cudaStream_t side1 = 0, side2 = 0;
    static cudaEvent_t evC[4], evF0 = 0, evF1 = 0, evA0 = 0, evA1 = 0;
    static int attr_done = 0;
    if (!attr_done) {
        cudaFuncSetAttribute(fps_kernel<32>, cudaFuncAttributeMaxDynamicSharedMemorySize, 4096*12 + 64);
        cudaFuncSetAttribute(fps_kernel<16>, cudaFuncAttributeMaxDynamicSharedMemorySize, 2048*12 + 64);
        cudaFuncSetAttribute(s1_fused,  cudaFuncAttributeMaxDynamicSharedMemorySize, 97280);
        cudaFuncSetAttribute(s2a_fused, cudaFuncAttributeMaxDynamicSharedMemorySize, 216320);
        cudaFuncSetAttribute(s2b_fused, cudaFuncAttributeMaxDynamicSharedMemorySize, 174080);
        cudaStreamCreateWithFlags(&side1, cudaStreamNonBlocking);
        cudaStreamCreateWithFlags(&side2, cudaStreamNonBlocking);
        for (int k = 0; k < 4; k++) cudaEventCreateWithFlags(&evC[k], cudaEventDisableTiming);
        cudaEventCreateWithFlags(&evF0, cudaEventDisableTiming);
        cudaEventCreateWithFlags(&evF1, cudaEventDisableTiming);
        cudaEventCreateWithFlags(&evA0, cudaEventDisableTiming);
        cudaEventCreateWithFlags(&evA1, cudaEventDisableTiming);
        attr_done = 1;
    }

    float r2a = (float)(0.1*0.1), r2b = (float)(0.2*0.2);

    // ---- fps32 in 4 chunks on main stream ----
    for (int k = 0; k < 4; k++) {
        fps_kernel<32><<<8, 128, 4096*12 + 64>>>(pts, pos1, 4096, k*512, (k+1)*512);
        cudaEventRecord(evC[k], 0);
    }

    // ---- side2: fps16 in 2 chunks after pos1 complete ----
    cudaStreamWaitEvent(side2, evC[3], 0);
    fps_kernel<16><<<8, 128, 2048*12 + 64, side2>>>(pos1, pos2, 2048, 0, 256);
    cudaEventRecord(evF0, side2);
    fps_kernel<16><<<8, 128, 2048*12 + 64, side2>>>(pos1, pos2, 2048, 256, 512);
    cudaEventRecord(evF1, side2);

    // ---- side1: radius1 + s1 chunks trail the fps chunks, then s2 pipeline --
    for (int k = 0; k < 4; k++) {
        cudaStreamWaitEvent(side1, evC[k], 0);
        radius_kernel<<<512, 256, 0, side1>>>(pts, pos1, 4096, 2048, r2a, nidx1, cnt1, k*512, 512);
        s1_fused<<<1024, 256, 97280, side1>>>(pts, s1w1, s1b1, s1w2, s1b2, s1w3, s1b3, k*512);
    }
    cudaStreamWaitEvent(side1, evF0, 0);
    radius_kernel<<<256, 256, 0, side1>>>(pos1, pos2, 2048, 512, r2b, nidx2, cnt2, 0, 256);
    s2a_fused<<<512, 256, 216320, side1>>>(s2w1, s2b1, s2w2, s2b2, h2s2, 0);
    cudaEventRecord(evA0, side1);
    cudaStreamWaitEvent(side1, evF1, 0);
    radius_kernel<<<256, 256, 0, side1>>>(pos1, pos2, 2048, 512, r2b, nidx2, cnt2, 256, 256);
    s2a_fused<<<512, 256, 216320, side1>>>(s2w1, s2b1, s2w2, s2b2, h2s2, 256);
    cudaEventRecord(evA1, side1);

    // ---- main: s2b chunks overlap s2a chunk 1 ----
    cudaStreamWaitEvent(0, evA0, 0);
    s2b_fused<<<512, 256, 174080>>>(h2s2, s2w3, s2b3, 0);
    cudaStreamWaitEvent(0, evA1, 0);
    s2b_fused<<<512, 256, 174080>>>(h2s2, s2w3, s2b3, 256);

    // ---- global MLP (tf32) + fused pooling + head ----
    gemm_tf32<0><<<dim3(4, 32), 256>>>(x2cat, gw1, gb1, g1b, 4096, 256, 259, 1);
    gemm_tf32<0><<<dim3(8, 32), 256>>>(g1b, gw2, gb2, g2b, 4096, 512, 256, 1);
    gemm_tf32<1><<<dim3(16, 32), 256>>>(g2b, gw3, gb3, gmx, 4096, 1024, 512, 0);
    gemm_tf32<0><<<dim3(8, 1), 256>>>(gmx, l1w, l1b, f1, 128, 512, 1024, 1);
    gemm_tf32<0><<<dim3(4, 1), 256>>>(f1, l2w, l2b, f2, 128, 256, 512, 1);
    headfinal_kernel<<<1, 256>>>(l3w, l3b, (float*)d_out);
}